// round 12
// baseline (speedup 1.0000x reference)
#include <cuda_runtime.h>
#include <cuda_fp16.h>

static constexpr int NN   = 25000;
static constexpr int NE   = 500000;
static constexpr int CH   = 128;
static constexpr int OUTW = 2048;

// ---------------- scratch (static device globals; no allocation allowed) ----
__device__ __half g_hh[NN * CH];                  // 6.4 MB (h, fp16)
__device__ __half g_x3f[(size_t)NE * 64];         // 64 MB  (x3, fp16)
__device__ __half g_wh[(size_t)NE * 512];         // 512 MB (rank-ordered rows, fp16)
__device__ float  g_sh[(size_t)NE * 16];          // 32 MB  (rank-ordered edge_attrs)
__device__ __half g_aggh[(size_t)NN * 2048];      // 102.4 MB (agg, fp16)
__device__ uint2  g_Bf[8192];                     // W4 fp16 mma B-fragments (64 KB)
__device__ uint2  g_Of[16384];                    // Wout fp16 mma B-fragments (128 KB)
__device__ int    g_cnt[NN];                      // zero-init; scan re-zeroes
__device__ int    g_off[NN + 1];
__device__ int    g_ord[NE];                      // per-receiver ordinal
__device__ int    g_send[NE];
__device__ int    g_recv[NE];

__device__ __forceinline__ float silu(float x) {
    return __fdividef(x, 1.0f + __expf(-x));
}

// packed f32x2 helpers (Blackwell; PTX-only)
__device__ __forceinline__ unsigned long long bcast2(float a) {
    unsigned long long r;
    asm("mov.b64 %0, {%1, %1};" : "=l"(r) : "f"(a));
    return r;
}
__device__ __forceinline__ void fma2(unsigned long long& acc, unsigned long long a,
                                     unsigned long long b) {
    asm("fma.rn.f32x2 %0, %1, %2, %0;" : "+l"(acc) : "l"(a), "l"(b));
}
__device__ __forceinline__ float2 unpack2(unsigned long long v) {
    float lo, hi;
    asm("mov.b64 {%0, %1}, %2;" : "=f"(lo), "=f"(hi) : "l"(v));
    return make_float2(lo, hi);
}

// ---------------- mma helpers (legacy HMMA path, sm_80+; works on sm_100) ----
#define SWZ128(off) ((off) ^ (((off) >> 3) & 0x70))

__device__ __forceinline__ unsigned smem_u32(const void* p) {
    unsigned a;
    asm("{ .reg .u64 t; cvta.to.shared.u64 t, %1; cvt.u32.u64 %0, t; }"
        : "=r"(a) : "l"(p));
    return a;
}
__device__ __forceinline__ void ldmatrix_x4(unsigned* r, unsigned addr) {
    asm volatile("ldmatrix.sync.aligned.m8n8.x4.shared.b16 {%0,%1,%2,%3}, [%4];"
                 : "=r"(r[0]), "=r"(r[1]), "=r"(r[2]), "=r"(r[3]) : "r"(addr));
}
__device__ __forceinline__ void mma_f16(float* d, const unsigned* a,
                                        unsigned b0, unsigned b1) {
    asm volatile(
        "mma.sync.aligned.m16n8k16.row.col.f32.f16.f16.f32 "
        "{%0,%1,%2,%3}, {%4,%5,%6,%7}, {%8,%9}, {%0,%1,%2,%3};"
        : "+f"(d[0]), "+f"(d[1]), "+f"(d[2]), "+f"(d[3])
        : "r"(a[0]), "r"(a[1]), "r"(a[2]), "r"(a[3]), "r"(b0), "r"(b1));
}
__device__ __forceinline__ unsigned pack_h2(float x, float y) {
    __half2 q = __floats2half2_rn(x, y);
    return *(unsigned*)&q;
}

// ---------------- convert: dtype detect + int32 + fused hist/ordinal ---------
__global__ void k_convert(const int* __restrict__ ei) {
    int e = blockIdx.x * 256 + threadIdx.x;
    if (e >= NE) return;
    bool is64 = true;
#pragma unroll
    for (int i = 0; i < 8; i++) is64 &= (__ldg(&ei[2 * i + 1]) == 0);
    int s, r;
    if (is64) {
        const long long* p = (const long long*)ei;
        s = (int)p[e];
        r = (int)p[NE + e];
    } else {
        s = ei[e];
        r = ei[NE + e];
    }
    s = min(max(s, 0), NN - 1);
    r = min(max(r, 0), NN - 1);
    g_send[e] = s;
    g_recv[e] = r;
    g_ord[e] = atomicAdd(&g_cnt[r], 1);
}

// ---------------- scan (exclusive prefix over g_cnt; re-zeroes g_cnt) --------
__global__ void k_scan() {
    __shared__ int s[1024];
    const int t = threadIdx.x;
    const int CK = 25;
    const int base = t * CK;
    int loc[CK];
    int sum = 0;
#pragma unroll
    for (int i = 0; i < CK; i++) {
        int idx = base + i;
        int c = (idx < NN) ? g_cnt[idx] : 0;
        if (idx < NN) g_cnt[idx] = 0;
        loc[i] = sum;
        sum += c;
    }
    s[t] = sum;
    __syncthreads();
    for (int d = 1; d < 1024; d <<= 1) {
        int v = (t >= d) ? s[t - d] : 0;
        __syncthreads();
        s[t] += v;
        __syncthreads();
    }
    int pre = (t == 0) ? 0 : s[t - 1];
#pragma unroll
    for (int i = 0; i < CK; i++) {
        int idx = base + i;
        if (idx < NN) g_off[idx] = pre + loc[i];
    }
    if (t == 1023) g_off[NN] = s[1023];
}

// ---------------- k_pre: r123 + h GEMM + W4/Wout fragment prep ---------------
static constexpr int R123_BLKS = (NE + 63) / 64;   // 7813
static constexpr int H_BLKS    = (NN + 7) / 8;     // 3125
static constexpr int BF_BLKS   = 64;               // 8192 W4 fragments / 128 thr
static constexpr int OF_BLKS   = 128;              // 16384 Wout fragments / 128 thr

__global__ void __launch_bounds__(128) k_pre(
    const float* __restrict__ ef, const float* __restrict__ W1,
    const float* __restrict__ W2, const float* __restrict__ W3,
    const float* __restrict__ nf, const float* __restrict__ Wup,
    const float* __restrict__ W4, const float* __restrict__ Wout) {
    __shared__ float efs[64 * 8];
    __shared__ float bufA[64 * 64];
    __shared__ float bufB[64 * 64];
    __shared__ float fs[8 * CH];
    const int t = threadIdx.x;

    if (blockIdx.x < R123_BLKS) {
        const int e0 = blockIdx.x * 64;
        for (int i = t; i < 64 * 8; i += 128) {
            int e = e0 + i / 8;
            efs[i] = (e < NE) ? ef[(size_t)e * 8 + (i & 7)] : 0.0f;
        }
        __syncthreads();
        const int tr = t >> 4;
        const int tc = t & 15;
        {
            unsigned long long acc[8][2];
#pragma unroll
            for (int i = 0; i < 8; i++) { acc[i][0] = 0ULL; acc[i][1] = 0ULL; }
#pragma unroll
            for (int k = 0; k < 8; k++) {
                ulonglong2 w = __ldg((const ulonglong2*)&W1[k * 64 + tc * 4]);
#pragma unroll
                for (int i = 0; i < 8; i++) {
                    unsigned long long a2 = bcast2(efs[(tr * 8 + i) * 8 + k]);
                    fma2(acc[i][0], a2, w.x);
                    fma2(acc[i][1], a2, w.y);
                }
            }
#pragma unroll
            for (int i = 0; i < 8; i++) {
                float2 p0 = unpack2(acc[i][0]), p1 = unpack2(acc[i][1]);
                float* d = &bufA[(tr * 8 + i) * 64 + tc * 4];
                d[0] = silu(p0.x); d[1] = silu(p0.y);
                d[2] = silu(p1.x); d[3] = silu(p1.y);
            }
        }
        __syncthreads();
        {
            unsigned long long acc[8][2];
#pragma unroll
            for (int i = 0; i < 8; i++) { acc[i][0] = 0ULL; acc[i][1] = 0ULL; }
            for (int k = 0; k < 64; k++) {
                ulonglong2 w = __ldg((const ulonglong2*)&W2[k * 64 + tc * 4]);
#pragma unroll
                for (int i = 0; i < 8; i++) {
                    unsigned long long a2 = bcast2(bufA[(tr * 8 + i) * 64 + k]);
                    fma2(acc[i][0], a2, w.x);
                    fma2(acc[i][1], a2, w.y);
                }
            }
            __syncthreads();
#pragma unroll
            for (int i = 0; i < 8; i++) {
                float2 p0 = unpack2(acc[i][0]), p1 = unpack2(acc[i][1]);
                float* d = &bufB[(tr * 8 + i) * 64 + tc * 4];
                d[0] = silu(p0.x); d[1] = silu(p0.y);
                d[2] = silu(p1.x); d[3] = silu(p1.y);
            }
        }
        __syncthreads();
        {
            unsigned long long acc[8][2];
#pragma unroll
            for (int i = 0; i < 8; i++) { acc[i][0] = 0ULL; acc[i][1] = 0ULL; }
            for (int k = 0; k < 64; k++) {
                ulonglong2 w = __ldg((const ulonglong2*)&W3[k * 64 + tc * 4]);
#pragma unroll
                for (int i = 0; i < 8; i++) {
                    unsigned long long a2 = bcast2(bufB[(tr * 8 + i) * 64 + k]);
                    fma2(acc[i][0], a2, w.x);
                    fma2(acc[i][1], a2, w.y);
                }
            }
#pragma unroll
            for (int i = 0; i < 8; i++) {
                int e = e0 + tr * 8 + i;
                if (e < NE) {
                    float2 p0 = unpack2(acc[i][0]), p1 = unpack2(acc[i][1]);
                    float s0 = silu(p0.x), s1 = silu(p0.y);
                    float s2 = silu(p1.x), s3 = silu(p1.y);
                    uint2 hv = make_uint2(pack_h2(s0, s1), pack_h2(s2, s3));
                    *(uint2*)&g_x3f[(size_t)e * 64 + tc * 4] = hv;
                }
            }
        }
    } else if (blockIdx.x < R123_BLKS + H_BLKS) {
        // ---- h = node_feats @ W_up (stored fp16) ----
        const int n0 = (blockIdx.x - R123_BLKS) * 8;
        for (int i = t; i < 8 * CH; i += 128) {
            int n = n0 + i / CH;
            fs[i] = (n < NN) ? nf[(size_t)n * CH + (i & (CH - 1))] : 0.0f;
        }
        __syncthreads();
        float acc[8];
#pragma unroll
        for (int i = 0; i < 8; i++) acc[i] = 0.0f;
        for (int k = 0; k < CH; k++) {
            float wv = __ldg(&Wup[k * CH + t]);
#pragma unroll
            for (int i = 0; i < 8; i++) acc[i] += fs[i * CH + k] * wv;
        }
#pragma unroll
        for (int i = 0; i < 8; i++) {
            int n = n0 + i;
            if (n < NN) g_hh[(size_t)n * CH + t] = __float2half_rn(acc[i]);
        }
    } else if (blockIdx.x < R123_BLKS + H_BLKS + BF_BLKS) {
        // ---- W4 -> fp16 mma B-fragments ----
        int idx = (blockIdx.x - R123_BLKS - H_BLKS) * 128 + t;
        if (idx < 8192) {
            int chunk = idx >> 10;
            int w     = idx & 1023;
            int ksnt  = w >> 5;
            int lane  = w & 31;
            int ks = ksnt >> 3, nt = ksnt & 7;
            int n  = chunk * 64 + nt * 8 + (lane >> 2);
            int k0 = ks * 16 + (lane & 3) * 2;
            float v00 = __ldg(&W4[(size_t)k0 * 512 + n]);
            float v01 = __ldg(&W4[(size_t)(k0 + 1) * 512 + n]);
            float v08 = __ldg(&W4[(size_t)(k0 + 8) * 512 + n]);
            float v09 = __ldg(&W4[(size_t)(k0 + 9) * 512 + n]);
            g_Bf[idx] = make_uint2(pack_h2(v00, v01), pack_h2(v08, v09));
        }
    } else {
        // ---- Wout -> fp16 mma B-fragments (per path: K=128, N=128) ----
        int idx = (blockIdx.x - R123_BLKS - H_BLKS - BF_BLKS) * 128 + t;
        if (idx < 16384) {
            int path = idx >> 12;
            int w    = idx & 4095;
            int ks   = w >> 9;          // 0..7
            int rest = w & 511;
            int ntg  = rest >> 5;       // 0..15
            int lane = rest & 31;
            int d  = ntg * 8 + (lane >> 2);
            int k0 = ks * 16 + (lane & 3) * 2;
            const float* Wl = Wout + path * CH * CH;
            float v00 = __ldg(&Wl[(size_t)k0 * 128 + d]);
            float v01 = __ldg(&Wl[(size_t)(k0 + 1) * 128 + d]);
            float v08 = __ldg(&Wl[(size_t)(k0 + 8) * 128 + d]);
            float v09 = __ldg(&Wl[(size_t)(k0 + 9) * 128 + d]);
            g_Of[idx] = make_uint2(pack_h2(v00, v01), pack_h2(v08, v09));
        }
    }
}

// ---------------- layer 4: HMMA fp16 GEMM + gather, rank-ordered fp16 store --
// Block: M=128 edges x N=64 cols (chunk) x K=64.
// h (64 needed cols) staged coalesced into padded smem -> epilogue reads LDS.
static constexpr int R4_OFF_A0 = 0;          // 16384 B (128 x 128B, SW128 fp16)
static constexpr int R4_OFF_B  = 16384;      // 8192 B
static constexpr int R4_OFF_H  = 24576;      // 128 rows x 72 halves = 18432 B
static constexpr int HPITCH    = 72;         // halves; banks spread (4r+c)
static constexpr int R4_STG_U  = 36;         // uints per staged row (reuses A+B)
static constexpr int R4_OFF_RS = 43008;      // 512 B (rank per row)
static constexpr int R4_SMEM   = 43520;

__global__ void __launch_bounds__(256, 4) k_r4() {
    extern __shared__ __align__(16) unsigned char smem[];
    uint2*  Bs  = (uint2*)(smem + R4_OFF_B);
    __half* Hs  = (__half*)(smem + R4_OFF_H);
    int*    rsm = (int*)(smem + R4_OFF_RS);
    const int t     = threadIdx.x;
    const int chunk = blockIdx.x;          // 0..7 -> cols chunk*64..+63
    const int e0    = blockIdx.y * 128;

    // ---- stage B fragments for this chunk (8 KB, uint4 granules) ----
    {
        const uint4* src = (const uint4*)(g_Bf + chunk * 1024);
        uint4* dst = (uint4*)Bs;
        for (int i = t; i < 512; i += 256) dst[i] = src[i];
    }
    // ---- A tile: copy fp16 x3, SW128 swizzle (16B granules) ----
    for (int i = t; i < 1024; i += 256) {
        int r = i >> 3;
        int c = i & 7;
        int e = e0 + r;
        uint4 v = make_uint4(0u, 0u, 0u, 0u);
        if (e < NE) v = *(const uint4*)&g_x3f[(size_t)e * 64 + c * 8];
        unsigned off = SWZ128((unsigned)(r * 128 + c * 16));
        *(uint4*)(smem + R4_OFF_A0 + off) = v;
    }
    // ---- h tile: needed 64 cols per row, coalesced, padded pitch ----
    {
        const int hc0 = (chunk & 1) * 64;
        for (int i = t; i < 1024; i += 256) {
            int r = i >> 3;
            int q = i & 7;
            int e = e0 + r;
            uint4 v = make_uint4(0u, 0u, 0u, 0u);
            if (e < NE) {
                int s = g_send[e];
                v = *(const uint4*)&g_hh[(size_t)s * CH + hc0 + q * 8];
            }
            *(uint4*)&Hs[r * HPITCH + q * 8] = v;
        }
    }
    if (t < 128) {
        int e = e0 + t;
        rsm[t] = (e < NE) ? (g_off[g_recv[e]] + g_ord[e]) : 0;
    }
    __syncthreads();

    const int lane = t & 31, wid = t >> 5;
    const int mrow0 = wid * 16;
    const int arow = mrow0 + (lane & 15);
    const int acol = (lane >> 4) << 3;
    const unsigned abyte = (unsigned)(arow * 128 + acol * 2);
    const unsigned sbase = smem_u32(smem);

    float acc[8][4];
#pragma unroll
    for (int i = 0; i < 8; i++)
#pragma unroll
        for (int j = 0; j < 4; j++) acc[i][j] = 0.0f;

#pragma unroll
    for (int ks = 0; ks < 4; ks++) {
        unsigned off = SWZ128(abyte + ks * 32);
        unsigned a0[4];
        ldmatrix_x4(a0, sbase + R4_OFF_A0 + off);
#pragma unroll
        for (int nt = 0; nt < 8; nt++) {
            uint2 b = Bs[(ks * 8 + nt) * 32 + lane];
            mma_f16(acc[nt], a0, b.x, b.y);
        }
    }
    __syncthreads();   // A/B smem dead; reuse as epilogue staging (half2)

    // ---- epilogue: x h[send] (from smem), pack half2, stage ----
    unsigned* stage = (unsigned*)smem;   // 128 x R4_STG_U uints
    const int r    = lane >> 2;
    const int row0 = mrow0 + r, row1 = row0 + 8;
    const int cp   = (lane & 3) << 1;
#pragma unroll
    for (int nt = 0; nt < 8; nt++) {
        int colu = nt * 4 + (lane & 3);
        float2 f0 = __half22float2(*(const __half2*)&Hs[row0 * HPITCH + nt * 8 + cp]);
        float2 f1 = __half22float2(*(const __half2*)&Hs[row1 * HPITCH + nt * 8 + cp]);
        stage[row0 * R4_STG_U + colu] = pack_h2(acc[nt][0] * f0.x, acc[nt][1] * f0.y);
        stage[row1 * R4_STG_U + colu] = pack_h2(acc[nt][2] * f1.x, acc[nt][3] * f1.y);
    }
    __syncthreads();

    // ---- coalesced g_wh store: 1024 uint4 (16 halves each), 4 iters ----
#pragma unroll
    for (int it = 0; it < 4; it++) {
        int idx = it * 256 + t;       // 0..1023
        int row = idx >> 3;
        int q   = idx & 7;
        if (e0 + row < NE) {
            uint4 v = *(uint4*)&stage[row * R4_STG_U + q * 4];
            *(uint4*)&g_wh[(size_t)rsm[row] * 512 + chunk * 64 + q * 8] = v;
        }
    }
}

// ---------------- scatter edge_attrs into rank order -------------------------
__global__ void k_scatter(const float* __restrict__ ea) {
    int e = blockIdx.x * 256 + threadIdx.x;
    if (e >= NE) return;
    int rk = g_off[g_recv[e]] + g_ord[e];
    const float4* src = (const float4*)&ea[(size_t)e * 16];
    float4* dst = (float4*)&g_sh[(size_t)rk * 16];
#pragma unroll
    for (int j = 0; j < 4; j++) dst[j] = src[j];
}

// ---------------- segmented aggregation: streaming fp16 reads, fp16 write ----
__global__ void k_agg() {
    const int n = blockIdx.x;
    const int c = threadIdx.x;
    float acc[16];
#pragma unroll
    for (int m = 0; m < 16; m++) acc[m] = 0.0f;
    const int lo = g_off[n], hi = g_off[n + 1];

    int i = lo;
    for (; i + 2 <= hi; i += 2) {
        const __half* wa = g_wh + (size_t)i * 512;
        const __half* wb = wa + 512;
        float a0 = __half2float(wa[c]),       a1 = __half2float(wa[128 + c]);
        float a2 = __half2float(wa[256 + c]), a3 = __half2float(wa[384 + c]);
        float b0 = __half2float(wb[c]),       b1 = __half2float(wb[128 + c]);
        float b2 = __half2float(wb[256 + c]), b3 = __half2float(wb[384 + c]);
        const float* sa = g_sh + (size_t)i * 16;
        const float* sb = sa + 16;
        acc[0] += __ldg(&sa[0]) * a0 + __ldg(&sb[0]) * b0;
#pragma unroll
        for (int m = 1; m < 4; m++) acc[m] += __ldg(&sa[m]) * a1 + __ldg(&sb[m]) * b1;
#pragma unroll
        for (int m = 4; m < 9; m++) acc[m] += __ldg(&sa[m]) * a2 + __ldg(&sb[m]) * b2;
#pragma unroll
        for (int m = 9; m < 16; m++) acc[m] += __ldg(&sa[m]) * a3 + __ldg(&sb[m]) * b3;
    }
    if (i < hi) {
        const __half* wa = g_wh + (size_t)i * 512;
        float a0 = __half2float(wa[c]),       a1 = __half2float(wa[128 + c]);
        float a2 = __half2float(wa[256 + c]), a3 = __half2float(wa[384 + c]);
        const float* sa = g_sh + (size_t)i * 16;
        acc[0] += __ldg(&sa[0]) * a0;
#pragma unroll
        for (int m = 1; m < 4; m++) acc[m] += __ldg(&sa[m]) * a1;
#pragma unroll
        for (int m = 4; m < 9; m++) acc[m] += __ldg(&sa[m]) * a2;
#pragma unroll
        for (int m = 9; m < 16; m++) acc[m] += __ldg(&sa[m]) * a3;
    }
    const float inv = 0.05f;
#pragma unroll
    for (int m = 0; m < 16; m++)
        g_aggh[(size_t)n * 2048 + m * 128 + c] = __float2half_rn(acc[m] * inv);
}

// ---------------- out transform: HMMA fp16 (single launch, range dispatch) ---
template <int ML, int NB, int OFFM, int COLOFF, int PATH>
__device__ __forceinline__ void out_body(int blk, unsigned char* osm,
                                         float* __restrict__ out) {
    constexpr int NR = ML * NB;  // <= 64
    const int t  = threadIdx.x;
    const int n0 = blk * NB;

    // ---- A tile: 64 rows x 128 halves -> 128 phys rows x 128B, SW128 ----
    for (int g = t; g < 1024; g += 256) {
        int r  = g >> 4;
        int c8 = g & 15;
        uint4 v = make_uint4(0u, 0u, 0u, 0u);
        if (r < NR) {
            int n = n0 + r / ML;
            if (n < NN)
                v = *(const uint4*)&g_aggh[(size_t)n * 2048 +
                                           (OFFM + r % ML) * 128 + c8 * 8];
        }
        unsigned off = SWZ128((unsigned)((r * 2 + (c8 >> 3)) * 128 + (c8 & 7) * 16));
        *(uint4*)(osm + off) = v;
    }
    __syncthreads();

    const int lane = t & 31, wid = t >> 5;
    const int rt = wid & 3, ch = wid >> 2;
    const int lr = rt * 16 + (lane & 15);
    const unsigned sbase = smem_u32(osm);

    float acc[8][4];
#pragma unroll
    for (int i = 0; i < 8; i++)
#pragma unroll
        for (int j = 0; j < 4; j++) acc[i][j] = 0.0f;

#pragma unroll
    for (int ks = 0; ks < 8; ks++) {
        unsigned abyte = (unsigned)((lr * 2 + (ks >= 4 ? 1 : 0)) * 128 +
                                    (ks & 3) * 32 + ((lane >> 4) << 4));
        unsigned a[4];
        ldmatrix_x4(a, sbase + SWZ128(abyte));
#pragma unroll
        for (int nt = 0; nt < 8; nt++) {
            uint2 b = __ldg(&g_Of[(((PATH * 8 + ks) * 16 + ch * 8 + nt) * 32) + lane]);
            mma_f16(acc[nt], a, b.x, b.y);
        }
    }
    __syncthreads();   // A smem dead; reuse as fp32 stage [64][129]

    float* As = (float*)osm;
    const int r0 = rt * 16 + (lane >> 2), r1 = r0 + 8;
    const int cp = (lane & 3) << 1;
#pragma unroll
    for (int nt = 0; nt < 8; nt++) {
        int col = ch * 64 + nt * 8 + cp;
        As[r0 * 129 + col]     = acc[nt][0];
        As[r0 * 129 + col + 1] = acc[nt][1];
        As[r1 * 129 + col]     = acc[nt][2];
        As[r1 * 129 + col + 1] = acc[nt][3];
    }
    __syncthreads();

    for (int idx = t; idx < NB * ML * 128; idx += 256) {
        int n_l = idx / (ML * 128);
        int rem = idx - n_l * (ML * 128);
        int d = rem / ML;
        int m = rem - d * ML;
        int n = n0 + n_l;
        if (n < NN)
            out[(size_t)n * OUTW + COLOFF + rem] = As[(n_l * ML + m) * 129 + d];
    }
}

static constexpr int OUT_B0 = (NN + 63) / 64;    // 391
static constexpr int OUT_B1 = (NN + 20) / 21;    // 1191
static constexpr int OUT_B2 = (NN + 11) / 12;    // 2084
static constexpr int OUT_B3 = (NN + 8) / 9;      // 2778
static constexpr int OUT_BLKS = OUT_B0 + OUT_B1 + OUT_B2 + OUT_B3;

__global__ void __launch_bounds__(256, 4) k_out_all(float* __restrict__ out) {
    __shared__ __align__(16) unsigned char osm[64 * 129 * 4];  // 33 KB
    int b = blockIdx.x;
    if (b < OUT_B0) {
        out_body<1, 64, 0, 0, 0>(b, osm, out);
    } else if (b < OUT_B0 + OUT_B1) {
        out_body<3, 21, 1, 128, 1>(b - OUT_B0, osm, out);
    } else if (b < OUT_B0 + OUT_B1 + OUT_B2) {
        out_body<5, 12, 4, 512, 2>(b - OUT_B0 - OUT_B1, osm, out);
    } else {
        out_body<7, 9, 9, 1152, 3>(b - OUT_B0 - OUT_B1 - OUT_B2, osm, out);
    }
}

// ---------------- one-body term ----------------------------------------------
__global__ void k_ob(const float* __restrict__ pf, const float* __restrict__ nf,
                     const float* __restrict__ lc, const float* __restrict__ Wp,
                     const float* __restrict__ Wn, const float* __restrict__ Wc,
                     float* __restrict__ out) {
    __shared__ float pfs[16 * 16];
    __shared__ float nfs[16 * 128];
    __shared__ float lcs[16];
    const int t  = threadIdx.x;
    const int n0 = blockIdx.x * 16;
    for (int i = t; i < 16 * 16; i += 128) {
        int n = n0 + i / 16;
        pfs[i] = (n < NN) ? pf[(size_t)n * 16 + (i & 15)] * 0.1f : 0.0f;
    }
    for (int i = t; i < 16 * 128; i += 128) {
        int n = n0 + i / 128;
        nfs[i] = (n < NN) ? nf[(size_t)n * 128 + (i & 127)] : 0.0f;
    }
    if (t < 16) {
        int n = n0 + t;
        lcs[t] = (n < NN) ? lc[n] : 0.0f;
    }
    __syncthreads();
    float acc[16];
    float wc = __ldg(&Wc[t]);
#pragma unroll
    for (int i = 0; i < 16; i++) acc[i] = lcs[i] * wc;
    for (int k = 0; k < 16; k++) {
        float wv = __ldg(&Wp[k * 128 + t]);
#pragma unroll
        for (int i = 0; i < 16; i++) acc[i] += pfs[i * 16 + k] * wv;
    }
    for (int k = 0; k < 128; k++) {
        float wv = __ldg(&Wn[k * 128 + t]);
#pragma unroll
        for (int i = 0; i < 16; i++) acc[i] += nfs[i * 128 + k] * wv;
    }
#pragma unroll
    for (int i = 0; i < 16; i++) {
        int n = n0 + i;
        if (n < NN) out[(size_t)n * OUTW + t] += acc[i];
    }
}

// ---------------- launch -----------------------------------------------------
extern "C" void kernel_launch(void* const* d_in, const int* in_sizes, int n_in,
                              void* d_out, int out_size) {
    const float* node_feats = (const float*)d_in[1];
    const float* edge_attrs = (const float*)d_in[2];
    const float* edge_feats = (const float*)d_in[3];
    const int*   edge_index = (const int*)d_in[4];
    const float* potential  = (const float*)d_in[5];
    const float* charges    = (const float*)d_in[6];
    const float* W_up = (const float*)d_in[7];
    const float* W1   = (const float*)d_in[8];
    const float* W2   = (const float*)d_in[9];
    const float* W3   = (const float*)d_in[10];
    const float* W4   = (const float*)d_in[11];
    const float* Wout = (const float*)d_in[12];
    const float* Wp   = (const float*)d_in[13];
    const float* Wn   = (const float*)d_in[14];
    const float* Wc   = (const float*)d_in[15];
    float*       out  = (float*)d_out;

    cudaFuncSetAttribute(k_r4, cudaFuncAttributeMaxDynamicSharedMemorySize, R4_SMEM);

    k_convert<<<(NE + 255) / 256, 256>>>(edge_index);                  // 0
    k_scan<<<1, 1024>>>();                                             // 1
    k_pre<<<R123_BLKS + H_BLKS + BF_BLKS + OF_BLKS, 128>>>(            // 2
        edge_feats, W1, W2, W3, node_feats, W_up, W4, Wout);
    k_r4<<<dim3(8, (NE + 127) / 128), 256, R4_SMEM>>>();               // 3 <- profiled
    k_scatter<<<(NE + 255) / 256, 256>>>(edge_attrs);                  // 4
    k_agg<<<NN, 128>>>();                                              // 5

    k_out_all<<<OUT_BLKS, 256>>>(out);
    k_ob<<<(NN + 15) / 16, 128>>>(potential, node_feats, charges, Wp, Wn, Wc, out);
}

// round 13
// speedup vs baseline: 1.0995x; 1.0995x over previous
#include <cuda_runtime.h>
#include <cuda_fp16.h>

static constexpr int NN   = 25000;
static constexpr int NE   = 500000;
static constexpr int CH   = 128;
static constexpr int OUTW = 2048;

// ---------------- scratch (static device globals; no allocation allowed) ----
__device__ __half g_hh[NN * CH];                  // 6.4 MB (h, fp16)
__device__ __half g_x3f[(size_t)NE * 64];         // 64 MB  (x3, fp16)
__device__ __half g_wh[(size_t)NE * 512];         // 512 MB (rank-ordered rows, fp16)
__device__ float  g_sh[(size_t)NE * 16];          // 32 MB  (rank-ordered edge_attrs)
__device__ __half g_aggh[(size_t)NN * 2048];      // 102.4 MB (agg, fp16)
__device__ uint2  g_Bf[8192];                     // W4 fp16 mma B-fragments (64 KB)
__device__ uint2  g_Of[16384];                    // Wout fp16 mma B-fragments (128 KB)
__device__ int    g_cnt[NN];                      // zero-init; scan re-zeroes
__device__ int    g_off[NN + 1];
__device__ int    g_ord[NE];                      // per-receiver ordinal
__device__ int    g_send[NE];
__device__ int    g_recv[NE];

__device__ __forceinline__ float silu(float x) {
    return __fdividef(x, 1.0f + __expf(-x));
}

// packed f32x2 helpers (Blackwell; PTX-only)
__device__ __forceinline__ unsigned long long bcast2(float a) {
    unsigned long long r;
    asm("mov.b64 %0, {%1, %1};" : "=l"(r) : "f"(a));
    return r;
}
__device__ __forceinline__ void fma2(unsigned long long& acc, unsigned long long a,
                                     unsigned long long b) {
    asm("fma.rn.f32x2 %0, %1, %2, %0;" : "+l"(acc) : "l"(a), "l"(b));
}
__device__ __forceinline__ float2 unpack2(unsigned long long v) {
    float lo, hi;
    asm("mov.b64 {%0, %1}, %2;" : "=f"(lo), "=f"(hi) : "l"(v));
    return make_float2(lo, hi);
}

// ---------------- mma helpers (legacy HMMA path, sm_80+; works on sm_100) ----
#define SWZ128(off) ((off) ^ (((off) >> 3) & 0x70))

__device__ __forceinline__ unsigned smem_u32(const void* p) {
    unsigned a;
    asm("{ .reg .u64 t; cvta.to.shared.u64 t, %1; cvt.u32.u64 %0, t; }"
        : "=r"(a) : "l"(p));
    return a;
}
__device__ __forceinline__ void ldmatrix_x4(unsigned* r, unsigned addr) {
    asm volatile("ldmatrix.sync.aligned.m8n8.x4.shared.b16 {%0,%1,%2,%3}, [%4];"
                 : "=r"(r[0]), "=r"(r[1]), "=r"(r[2]), "=r"(r[3]) : "r"(addr));
}
__device__ __forceinline__ void mma_f16(float* d, const unsigned* a,
                                        unsigned b0, unsigned b1) {
    asm volatile(
        "mma.sync.aligned.m16n8k16.row.col.f32.f16.f16.f32 "
        "{%0,%1,%2,%3}, {%4,%5,%6,%7}, {%8,%9}, {%0,%1,%2,%3};"
        : "+f"(d[0]), "+f"(d[1]), "+f"(d[2]), "+f"(d[3])
        : "r"(a[0]), "r"(a[1]), "r"(a[2]), "r"(a[3]), "r"(b0), "r"(b1));
}
__device__ __forceinline__ unsigned pack_h2(float x, float y) {
    __half2 q = __floats2half2_rn(x, y);
    return *(unsigned*)&q;
}

// ---------------- convert: dtype detect + int32 + fused hist/ordinal ---------
__global__ void k_convert(const int* __restrict__ ei) {
    int e = blockIdx.x * 256 + threadIdx.x;
    if (e >= NE) return;
    bool is64 = true;
#pragma unroll
    for (int i = 0; i < 8; i++) is64 &= (__ldg(&ei[2 * i + 1]) == 0);
    int s, r;
    if (is64) {
        const long long* p = (const long long*)ei;
        s = (int)p[e];
        r = (int)p[NE + e];
    } else {
        s = ei[e];
        r = ei[NE + e];
    }
    s = min(max(s, 0), NN - 1);
    r = min(max(r, 0), NN - 1);
    g_send[e] = s;
    g_recv[e] = r;
    g_ord[e] = atomicAdd(&g_cnt[r], 1);
}

// ---------------- scan (exclusive prefix over g_cnt; re-zeroes g_cnt) --------
__global__ void k_scan() {
    __shared__ int s[1024];
    const int t = threadIdx.x;
    const int CK = 25;
    const int base = t * CK;
    int loc[CK];
    int sum = 0;
#pragma unroll
    for (int i = 0; i < CK; i++) {
        int idx = base + i;
        int c = (idx < NN) ? g_cnt[idx] : 0;
        if (idx < NN) g_cnt[idx] = 0;
        loc[i] = sum;
        sum += c;
    }
    s[t] = sum;
    __syncthreads();
    for (int d = 1; d < 1024; d <<= 1) {
        int v = (t >= d) ? s[t - d] : 0;
        __syncthreads();
        s[t] += v;
        __syncthreads();
    }
    int pre = (t == 0) ? 0 : s[t - 1];
#pragma unroll
    for (int i = 0; i < CK; i++) {
        int idx = base + i;
        if (idx < NN) g_off[idx] = pre + loc[i];
    }
    if (t == 1023) g_off[NN] = s[1023];
}

// ---------------- k_pre: r123 + h GEMM + W4/Wout fragment prep ---------------
static constexpr int R123_BLKS = (NE + 63) / 64;   // 7813
static constexpr int H_BLKS    = (NN + 7) / 8;     // 3125
static constexpr int BF_BLKS   = 64;               // 8192 W4 fragments / 128 thr
static constexpr int OF_BLKS   = 128;              // 16384 Wout fragments / 128 thr

__global__ void __launch_bounds__(128) k_pre(
    const float* __restrict__ ef, const float* __restrict__ W1,
    const float* __restrict__ W2, const float* __restrict__ W3,
    const float* __restrict__ nf, const float* __restrict__ Wup,
    const float* __restrict__ W4, const float* __restrict__ Wout) {
    __shared__ float efs[64 * 8];
    __shared__ float bufA[64 * 64];
    __shared__ float bufB[64 * 64];
    __shared__ float fs[8 * CH];
    const int t = threadIdx.x;

    if (blockIdx.x < R123_BLKS) {
        const int e0 = blockIdx.x * 64;
        for (int i = t; i < 64 * 8; i += 128) {
            int e = e0 + i / 8;
            efs[i] = (e < NE) ? ef[(size_t)e * 8 + (i & 7)] : 0.0f;
        }
        __syncthreads();
        const int tr = t >> 4;
        const int tc = t & 15;
        {
            unsigned long long acc[8][2];
#pragma unroll
            for (int i = 0; i < 8; i++) { acc[i][0] = 0ULL; acc[i][1] = 0ULL; }
#pragma unroll
            for (int k = 0; k < 8; k++) {
                ulonglong2 w = __ldg((const ulonglong2*)&W1[k * 64 + tc * 4]);
#pragma unroll
                for (int i = 0; i < 8; i++) {
                    unsigned long long a2 = bcast2(efs[(tr * 8 + i) * 8 + k]);
                    fma2(acc[i][0], a2, w.x);
                    fma2(acc[i][1], a2, w.y);
                }
            }
#pragma unroll
            for (int i = 0; i < 8; i++) {
                float2 p0 = unpack2(acc[i][0]), p1 = unpack2(acc[i][1]);
                float* d = &bufA[(tr * 8 + i) * 64 + tc * 4];
                d[0] = silu(p0.x); d[1] = silu(p0.y);
                d[2] = silu(p1.x); d[3] = silu(p1.y);
            }
        }
        __syncthreads();
        {
            unsigned long long acc[8][2];
#pragma unroll
            for (int i = 0; i < 8; i++) { acc[i][0] = 0ULL; acc[i][1] = 0ULL; }
            for (int k = 0; k < 64; k++) {
                ulonglong2 w = __ldg((const ulonglong2*)&W2[k * 64 + tc * 4]);
#pragma unroll
                for (int i = 0; i < 8; i++) {
                    unsigned long long a2 = bcast2(bufA[(tr * 8 + i) * 64 + k]);
                    fma2(acc[i][0], a2, w.x);
                    fma2(acc[i][1], a2, w.y);
                }
            }
            __syncthreads();
#pragma unroll
            for (int i = 0; i < 8; i++) {
                float2 p0 = unpack2(acc[i][0]), p1 = unpack2(acc[i][1]);
                float* d = &bufB[(tr * 8 + i) * 64 + tc * 4];
                d[0] = silu(p0.x); d[1] = silu(p0.y);
                d[2] = silu(p1.x); d[3] = silu(p1.y);
            }
        }
        __syncthreads();
        {
            unsigned long long acc[8][2];
#pragma unroll
            for (int i = 0; i < 8; i++) { acc[i][0] = 0ULL; acc[i][1] = 0ULL; }
            for (int k = 0; k < 64; k++) {
                ulonglong2 w = __ldg((const ulonglong2*)&W3[k * 64 + tc * 4]);
#pragma unroll
                for (int i = 0; i < 8; i++) {
                    unsigned long long a2 = bcast2(bufB[(tr * 8 + i) * 64 + k]);
                    fma2(acc[i][0], a2, w.x);
                    fma2(acc[i][1], a2, w.y);
                }
            }
#pragma unroll
            for (int i = 0; i < 8; i++) {
                int e = e0 + tr * 8 + i;
                if (e < NE) {
                    float2 p0 = unpack2(acc[i][0]), p1 = unpack2(acc[i][1]);
                    float s0 = silu(p0.x), s1 = silu(p0.y);
                    float s2 = silu(p1.x), s3 = silu(p1.y);
                    uint2 hv = make_uint2(pack_h2(s0, s1), pack_h2(s2, s3));
                    *(uint2*)&g_x3f[(size_t)e * 64 + tc * 4] = hv;
                }
            }
        }
    } else if (blockIdx.x < R123_BLKS + H_BLKS) {
        // ---- h = node_feats @ W_up (stored fp16) ----
        const int n0 = (blockIdx.x - R123_BLKS) * 8;
        for (int i = t; i < 8 * CH; i += 128) {
            int n = n0 + i / CH;
            fs[i] = (n < NN) ? nf[(size_t)n * CH + (i & (CH - 1))] : 0.0f;
        }
        __syncthreads();
        float acc[8];
#pragma unroll
        for (int i = 0; i < 8; i++) acc[i] = 0.0f;
        for (int k = 0; k < CH; k++) {
            float wv = __ldg(&Wup[k * CH + t]);
#pragma unroll
            for (int i = 0; i < 8; i++) acc[i] += fs[i * CH + k] * wv;
        }
#pragma unroll
        for (int i = 0; i < 8; i++) {
            int n = n0 + i;
            if (n < NN) g_hh[(size_t)n * CH + t] = __float2half_rn(acc[i]);
        }
    } else if (blockIdx.x < R123_BLKS + H_BLKS + BF_BLKS) {
        // ---- W4 -> fp16 mma B-fragments ----
        int idx = (blockIdx.x - R123_BLKS - H_BLKS) * 128 + t;
        if (idx < 8192) {
            int chunk = idx >> 10;
            int w     = idx & 1023;
            int ksnt  = w >> 5;
            int lane  = w & 31;
            int ks = ksnt >> 3, nt = ksnt & 7;
            int n  = chunk * 64 + nt * 8 + (lane >> 2);
            int k0 = ks * 16 + (lane & 3) * 2;
            float v00 = __ldg(&W4[(size_t)k0 * 512 + n]);
            float v01 = __ldg(&W4[(size_t)(k0 + 1) * 512 + n]);
            float v08 = __ldg(&W4[(size_t)(k0 + 8) * 512 + n]);
            float v09 = __ldg(&W4[(size_t)(k0 + 9) * 512 + n]);
            g_Bf[idx] = make_uint2(pack_h2(v00, v01), pack_h2(v08, v09));
        }
    } else {
        // ---- Wout -> fp16 mma B-fragments (per path: K=128, N=128) ----
        int idx = (blockIdx.x - R123_BLKS - H_BLKS - BF_BLKS) * 128 + t;
        if (idx < 16384) {
            int path = idx >> 12;
            int w    = idx & 4095;
            int ks   = w >> 9;          // 0..7
            int rest = w & 511;
            int ntg  = rest >> 5;       // 0..15
            int lane = rest & 31;
            int d  = ntg * 8 + (lane >> 2);
            int k0 = ks * 16 + (lane & 3) * 2;
            const float* Wl = Wout + path * CH * CH;
            float v00 = __ldg(&Wl[(size_t)k0 * 128 + d]);
            float v01 = __ldg(&Wl[(size_t)(k0 + 1) * 128 + d]);
            float v08 = __ldg(&Wl[(size_t)(k0 + 8) * 128 + d]);
            float v09 = __ldg(&Wl[(size_t)(k0 + 9) * 128 + d]);
            g_Of[idx] = make_uint2(pack_h2(v00, v01), pack_h2(v08, v09));
        }
    }
}

// ---------------- layer 4: HMMA fp16 GEMM, chunk-merged -----------------------
// One block: M=128 edges x ALL 512 cols (8 chunks of 64), K=64.
// A staged once; per chunk: B stage, mainloop, x h[send] epilogue, staged store.
static constexpr int R4_OFF_A0  = 0;          // 16384 B (128 x 128B, SW128 fp16)
static constexpr int R4_OFF_B   = 16384;      // 8192 B
static constexpr int R4_OFF_STG = 24576;      // 128 x 36 uints = 18432 B
static constexpr int R4_STG_U   = 36;
static constexpr int R4_OFF_SS  = 43008;      // 512 B (send per row)
static constexpr int R4_OFF_RS  = 43520;      // 512 B (rank per row)
static constexpr int R4_SMEM    = 44032;

__global__ void __launch_bounds__(256, 4) k_r4() {
    extern __shared__ __align__(16) unsigned char smem[];
    uint2*    Bs    = (uint2*)(smem + R4_OFF_B);
    unsigned* stage = (unsigned*)(smem + R4_OFF_STG);
    int*      ssm   = (int*)(smem + R4_OFF_SS);
    int*      rsm   = (int*)(smem + R4_OFF_RS);
    const int t  = threadIdx.x;
    const int e0 = blockIdx.x * 128;

    // ---- A tile staged ONCE: fp16 x3, SW128 swizzle (16B granules) ----
    for (int i = t; i < 1024; i += 256) {
        int r = i >> 3;
        int c = i & 7;
        int e = e0 + r;
        uint4 v = make_uint4(0u, 0u, 0u, 0u);
        if (e < NE) v = *(const uint4*)&g_x3f[(size_t)e * 64 + c * 8];
        unsigned off = SWZ128((unsigned)(r * 128 + c * 16));
        *(uint4*)(smem + R4_OFF_A0 + off) = v;
    }
    if (t < 128) {
        int e = e0 + t;
        ssm[t] = (e < NE) ? g_send[e] : 0;
        rsm[t] = (e < NE) ? (g_off[g_recv[e]] + g_ord[e]) : 0;
    }

    const int lane = t & 31, wid = t >> 5;
    const int mrow0 = wid * 16;
    const int arow = mrow0 + (lane & 15);
    const int acol = (lane >> 4) << 3;
    const unsigned abyte = (unsigned)(arow * 128 + acol * 2);
    const unsigned sbase = smem_u32(smem);
    const int r    = lane >> 2;
    const int row0 = mrow0 + r, row1 = row0 + 8;
    const int cp   = (lane & 3) << 1;

#pragma unroll 1
    for (int chunk = 0; chunk < 8; chunk++) {
        // ---- stage B fragments for this chunk (8 KB) ----
        {
            const uint4* src = (const uint4*)(g_Bf + chunk * 1024);
            uint4* dst = (uint4*)Bs;
            for (int i = t; i < 512; i += 256) dst[i] = src[i];
        }
        __syncthreads();   // covers A/ids (iter 0), B stage, prev store->stage reuse

        float acc[8][4];
#pragma unroll
        for (int i = 0; i < 8; i++)
#pragma unroll
            for (int j = 0; j < 4; j++) acc[i][j] = 0.0f;

#pragma unroll
        for (int ks = 0; ks < 4; ks++) {
            unsigned off = SWZ128(abyte + ks * 32);
            unsigned a0[4];
            ldmatrix_x4(a0, sbase + R4_OFF_A0 + off);
#pragma unroll
            for (int nt = 0; nt < 8; nt++) {
                uint2 b = Bs[(ks * 8 + nt) * 32 + lane];
                mma_f16(acc[nt], a0, b.x, b.y);
            }
        }

        // ---- epilogue: x h[send] (direct half2 L2-hit loads), pack, stage ----
        const int s0 = ssm[row0], s1 = ssm[row1];
        const int hb = (chunk & 1) * 64 + cp;
#pragma unroll
        for (int nt = 0; nt < 8; nt++) {
            int colu = nt * 4 + (lane & 3);
            float2 f0 = __half22float2(
                __ldg((const __half2*)&g_hh[(size_t)s0 * CH + hb + nt * 8]));
            float2 f1 = __half22float2(
                __ldg((const __half2*)&g_hh[(size_t)s1 * CH + hb + nt * 8]));
            stage[row0 * R4_STG_U + colu] = pack_h2(acc[nt][0] * f0.x, acc[nt][1] * f0.y);
            stage[row1 * R4_STG_U + colu] = pack_h2(acc[nt][2] * f1.x, acc[nt][3] * f1.y);
        }
        __syncthreads();

        // ---- coalesced g_wh store: 1024 uint4, 4 iters ----
#pragma unroll
        for (int it = 0; it < 4; it++) {
            int idx = it * 256 + t;
            int row = idx >> 3;
            int q   = idx & 7;
            if (e0 + row < NE) {
                uint4 v = *(uint4*)&stage[row * R4_STG_U + q * 4];
                *(uint4*)&g_wh[(size_t)rsm[row] * 512 + chunk * 64 + q * 8] = v;
            }
        }
        // next iteration's post-B-stage __syncthreads orders store vs stage reuse
    }
}

// ---------------- scatter edge_attrs into rank order -------------------------
__global__ void k_scatter(const float* __restrict__ ea) {
    int e = blockIdx.x * 256 + threadIdx.x;
    if (e >= NE) return;
    int rk = g_off[g_recv[e]] + g_ord[e];
    const float4* src = (const float4*)&ea[(size_t)e * 16];
    float4* dst = (float4*)&g_sh[(size_t)rk * 16];
#pragma unroll
    for (int j = 0; j < 4; j++) dst[j] = src[j];
}

// ---------------- segmented aggregation: streaming fp16 reads, fp16 write ----
__global__ void k_agg() {
    const int n = blockIdx.x;
    const int c = threadIdx.x;
    float acc[16];
#pragma unroll
    for (int m = 0; m < 16; m++) acc[m] = 0.0f;
    const int lo = g_off[n], hi = g_off[n + 1];

    int i = lo;
    for (; i + 2 <= hi; i += 2) {
        const __half* wa = g_wh + (size_t)i * 512;
        const __half* wb = wa + 512;
        float a0 = __half2float(wa[c]),       a1 = __half2float(wa[128 + c]);
        float a2 = __half2float(wa[256 + c]), a3 = __half2float(wa[384 + c]);
        float b0 = __half2float(wb[c]),       b1 = __half2float(wb[128 + c]);
        float b2 = __half2float(wb[256 + c]), b3 = __half2float(wb[384 + c]);
        const float* sa = g_sh + (size_t)i * 16;
        const float* sb = sa + 16;
        acc[0] += __ldg(&sa[0]) * a0 + __ldg(&sb[0]) * b0;
#pragma unroll
        for (int m = 1; m < 4; m++) acc[m] += __ldg(&sa[m]) * a1 + __ldg(&sb[m]) * b1;
#pragma unroll
        for (int m = 4; m < 9; m++) acc[m] += __ldg(&sa[m]) * a2 + __ldg(&sb[m]) * b2;
#pragma unroll
        for (int m = 9; m < 16; m++) acc[m] += __ldg(&sa[m]) * a3 + __ldg(&sb[m]) * b3;
    }
    if (i < hi) {
        const __half* wa = g_wh + (size_t)i * 512;
        float a0 = __half2float(wa[c]),       a1 = __half2float(wa[128 + c]);
        float a2 = __half2float(wa[256 + c]), a3 = __half2float(wa[384 + c]);
        const float* sa = g_sh + (size_t)i * 16;
        acc[0] += __ldg(&sa[0]) * a0;
#pragma unroll
        for (int m = 1; m < 4; m++) acc[m] += __ldg(&sa[m]) * a1;
#pragma unroll
        for (int m = 4; m < 9; m++) acc[m] += __ldg(&sa[m]) * a2;
#pragma unroll
        for (int m = 9; m < 16; m++) acc[m] += __ldg(&sa[m]) * a3;
    }
    const float inv = 0.05f;
#pragma unroll
    for (int m = 0; m < 16; m++)
        g_aggh[(size_t)n * 2048 + m * 128 + c] = __float2half_rn(acc[m] * inv);
}

// ---------------- out transform: HMMA fp16 (single launch, range dispatch) ---
template <int ML, int NB, int OFFM, int COLOFF, int PATH>
__device__ __forceinline__ void out_body(int blk, unsigned char* osm,
                                         float* __restrict__ out) {
    constexpr int NR = ML * NB;  // <= 64
    const int t  = threadIdx.x;
    const int n0 = blk * NB;

    // ---- A tile: 64 rows x 128 halves -> 128 phys rows x 128B, SW128 ----
    for (int g = t; g < 1024; g += 256) {
        int r  = g >> 4;
        int c8 = g & 15;
        uint4 v = make_uint4(0u, 0u, 0u, 0u);
        if (r < NR) {
            int n = n0 + r / ML;
            if (n < NN)
                v = *(const uint4*)&g_aggh[(size_t)n * 2048 +
                                           (OFFM + r % ML) * 128 + c8 * 8];
        }
        unsigned off = SWZ128((unsigned)((r * 2 + (c8 >> 3)) * 128 + (c8 & 7) * 16));
        *(uint4*)(osm + off) = v;
    }
    __syncthreads();

    const int lane = t & 31, wid = t >> 5;
    const int rt = wid & 3, ch = wid >> 2;
    const int lr = rt * 16 + (lane & 15);
    const unsigned sbase = smem_u32(osm);

    float acc[8][4];
#pragma unroll
    for (int i = 0; i < 8; i++)
#pragma unroll
        for (int j = 0; j < 4; j++) acc[i][j] = 0.0f;

#pragma unroll
    for (int ks = 0; ks < 8; ks++) {
        unsigned abyte = (unsigned)((lr * 2 + (ks >= 4 ? 1 : 0)) * 128 +
                                    (ks & 3) * 32 + ((lane >> 4) << 4));
        unsigned a[4];
        ldmatrix_x4(a, sbase + SWZ128(abyte));
#pragma unroll
        for (int nt = 0; nt < 8; nt++) {
            uint2 b = __ldg(&g_Of[(((PATH * 8 + ks) * 16 + ch * 8 + nt) * 32) + lane]);
            mma_f16(acc[nt], a, b.x, b.y);
        }
    }
    __syncthreads();   // A smem dead; reuse as fp32 stage [64][129]

    float* As = (float*)osm;
    const int r0 = rt * 16 + (lane >> 2), r1 = r0 + 8;
    const int cp = (lane & 3) << 1;
#pragma unroll
    for (int nt = 0; nt < 8; nt++) {
        int col = ch * 64 + nt * 8 + cp;
        As[r0 * 129 + col]     = acc[nt][0];
        As[r0 * 129 + col + 1] = acc[nt][1];
        As[r1 * 129 + col]     = acc[nt][2];
        As[r1 * 129 + col + 1] = acc[nt][3];
    }
    __syncthreads();

    for (int idx = t; idx < NB * ML * 128; idx += 256) {
        int n_l = idx / (ML * 128);
        int rem = idx - n_l * (ML * 128);
        int d = rem / ML;
        int m = rem - d * ML;
        int n = n0 + n_l;
        if (n < NN)
            out[(size_t)n * OUTW + COLOFF + rem] = As[(n_l * ML + m) * 129 + d];
    }
}

static constexpr int OUT_B0 = (NN + 63) / 64;    // 391
static constexpr int OUT_B1 = (NN + 20) / 21;    // 1191
static constexpr int OUT_B2 = (NN + 11) / 12;    // 2084
static constexpr int OUT_B3 = (NN + 8) / 9;      // 2778
static constexpr int OUT_BLKS = OUT_B0 + OUT_B1 + OUT_B2 + OUT_B3;

__global__ void __launch_bounds__(256, 4) k_out_all(float* __restrict__ out) {
    __shared__ __align__(16) unsigned char osm[64 * 129 * 4];  // 33 KB
    int b = blockIdx.x;
    if (b < OUT_B0) {
        out_body<1, 64, 0, 0, 0>(b, osm, out);
    } else if (b < OUT_B0 + OUT_B1) {
        out_body<3, 21, 1, 128, 1>(b - OUT_B0, osm, out);
    } else if (b < OUT_B0 + OUT_B1 + OUT_B2) {
        out_body<5, 12, 4, 512, 2>(b - OUT_B0 - OUT_B1, osm, out);
    } else {
        out_body<7, 9, 9, 1152, 3>(b - OUT_B0 - OUT_B1 - OUT_B2, osm, out);
    }
}

// ---------------- one-body term ----------------------------------------------
__global__ void k_ob(const float* __restrict__ pf, const float* __restrict__ nf,
                     const float* __restrict__ lc, const float* __restrict__ Wp,
                     const float* __restrict__ Wn, const float* __restrict__ Wc,
                     float* __restrict__ out) {
    __shared__ float pfs[16 * 16];
    __shared__ float nfs[16 * 128];
    __shared__ float lcs[16];
    const int t  = threadIdx.x;
    const int n0 = blockIdx.x * 16;
    for (int i = t; i < 16 * 16; i += 128) {
        int n = n0 + i / 16;
        pfs[i] = (n < NN) ? pf[(size_t)n * 16 + (i & 15)] * 0.1f : 0.0f;
    }
    for (int i = t; i < 16 * 128; i += 128) {
        int n = n0 + i / 128;
        nfs[i] = (n < NN) ? nf[(size_t)n * 128 + (i & 127)] : 0.0f;
    }
    if (t < 16) {
        int n = n0 + t;
        lcs[t] = (n < NN) ? lc[n] : 0.0f;
    }
    __syncthreads();
    float acc[16];
    float wc = __ldg(&Wc[t]);
#pragma unroll
    for (int i = 0; i < 16; i++) acc[i] = lcs[i] * wc;
    for (int k = 0; k < 16; k++) {
        float wv = __ldg(&Wp[k * 128 + t]);
#pragma unroll
        for (int i = 0; i < 16; i++) acc[i] += pfs[i * 16 + k] * wv;
    }
    for (int k = 0; k < 128; k++) {
        float wv = __ldg(&Wn[k * 128 + t]);
#pragma unroll
        for (int i = 0; i < 16; i++) acc[i] += nfs[i * 128 + k] * wv;
    }
#pragma unroll
    for (int i = 0; i < 16; i++) {
        int n = n0 + i;
        if (n < NN) out[(size_t)n * OUTW + t] += acc[i];
    }
}

// ---------------- launch -----------------------------------------------------
extern "C" void kernel_launch(void* const* d_in, const int* in_sizes, int n_in,
                              void* d_out, int out_size) {
    const float* node_feats = (const float*)d_in[1];
    const float* edge_attrs = (const float*)d_in[2];
    const float* edge_feats = (const float*)d_in[3];
    const int*   edge_index = (const int*)d_in[4];
    const float* potential  = (const float*)d_in[5];
    const float* charges    = (const float*)d_in[6];
    const float* W_up = (const float*)d_in[7];
    const float* W1   = (const float*)d_in[8];
    const float* W2   = (const float*)d_in[9];
    const float* W3   = (const float*)d_in[10];
    const float* W4   = (const float*)d_in[11];
    const float* Wout = (const float*)d_in[12];
    const float* Wp   = (const float*)d_in[13];
    const float* Wn   = (const float*)d_in[14];
    const float* Wc   = (const float*)d_in[15];
    float*       out  = (float*)d_out;

    cudaFuncSetAttribute(k_r4, cudaFuncAttributeMaxDynamicSharedMemorySize, R4_SMEM);

    k_convert<<<(NE + 255) / 256, 256>>>(edge_index);                  // 0
    k_scan<<<1, 1024>>>();                                             // 1
    k_pre<<<R123_BLKS + H_BLKS + BF_BLKS + OF_BLKS, 128>>>(            // 2
        edge_feats, W1, W2, W3, node_feats, W_up, W4, Wout);
    k_r4<<<(NE + 127) / 128, 256, R4_SMEM>>>();                        // 3 <- profiled
    k_scatter<<<(NE + 255) / 256, 256>>>(edge_attrs);                  // 4
    k_agg<<<NN, 128>>>();                                              // 5

    k_out_all<<<OUT_BLKS, 256>>>(out);
    k_ob<<<(NN + 15) / 16, 128>>>(potential, node_feats, charges, Wp, Wn, Wc, out);
}

// round 14
// speedup vs baseline: 1.2140x; 1.1041x over previous
#include <cuda_runtime.h>
#include <cuda_fp16.h>

static constexpr int NN   = 25000;
static constexpr int NE   = 500000;
static constexpr int CH   = 128;
static constexpr int OUTW = 2048;

// ---------------- scratch (static device globals; no allocation allowed) ----
__device__ __half g_hh[NN * CH];                  // 6.4 MB (h, fp16)
__device__ __half g_x3f[(size_t)NE * 64];         // 64 MB  (x3, fp16)
__device__ __half g_wh[(size_t)NE * 512];         // 512 MB (rank-ordered rows, fp16)
__device__ float  g_sh[(size_t)NE * 16];          // 32 MB  (rank-ordered edge_attrs)
__device__ __half g_aggh[(size_t)NN * 2048];      // 102.4 MB (agg, fp16)
__device__ uint2  g_Bf[8192];                     // W4 fp16 mma B-fragments (64 KB)
__device__ uint2  g_Of[16384];                    // Wout fp16 mma B-fragments (128 KB)
__device__ uint2  g_W2f[1024];                    // W2 fp16 mma B-fragments (8 KB)
__device__ uint2  g_W3f[1024];                    // W3 fp16 mma B-fragments (8 KB)
__device__ int    g_cnt[NN];                      // zero-init; scan re-zeroes
__device__ int    g_off[NN + 1];
__device__ int    g_ord[NE];                      // per-receiver ordinal
__device__ int    g_send[NE];
__device__ int    g_recv[NE];

__device__ __forceinline__ float silu(float x) {
    return __fdividef(x, 1.0f + __expf(-x));
}

// ---------------- mma helpers (legacy HMMA path, sm_80+; works on sm_100) ----
#define SWZ128(off) ((off) ^ (((off) >> 3) & 0x70))

__device__ __forceinline__ unsigned smem_u32(const void* p) {
    unsigned a;
    asm("{ .reg .u64 t; cvta.to.shared.u64 t, %1; cvt.u32.u64 %0, t; }"
        : "=r"(a) : "l"(p));
    return a;
}
__device__ __forceinline__ void ldmatrix_x4(unsigned* r, unsigned addr) {
    asm volatile("ldmatrix.sync.aligned.m8n8.x4.shared.b16 {%0,%1,%2,%3}, [%4];"
                 : "=r"(r[0]), "=r"(r[1]), "=r"(r[2]), "=r"(r[3]) : "r"(addr));
}
__device__ __forceinline__ void mma_f16(float* d, const unsigned* a,
                                        unsigned b0, unsigned b1) {
    asm volatile(
        "mma.sync.aligned.m16n8k16.row.col.f32.f16.f16.f32 "
        "{%0,%1,%2,%3}, {%4,%5,%6,%7}, {%8,%9}, {%0,%1,%2,%3};"
        : "+f"(d[0]), "+f"(d[1]), "+f"(d[2]), "+f"(d[3])
        : "r"(a[0]), "r"(a[1]), "r"(a[2]), "r"(a[3]), "r"(b0), "r"(b1));
}
__device__ __forceinline__ unsigned pack_h2(float x, float y) {
    __half2 q = __floats2half2_rn(x, y);
    return *(unsigned*)&q;
}

// ---------------- convert: dtype detect + hist/ordinal + W2/W3 frag prep -----
static constexpr int CONV_BLKS = (NE + 255) / 256;  // 1954

__global__ void __launch_bounds__(256) k_convert(const int* __restrict__ ei,
                                                 const float* __restrict__ W2,
                                                 const float* __restrict__ W3) {
    const int t = threadIdx.x;
    if (blockIdx.x < CONV_BLKS) {
        int e = blockIdx.x * 256 + t;
        if (e >= NE) return;
        bool is64 = true;
#pragma unroll
        for (int i = 0; i < 8; i++) is64 &= (__ldg(&ei[2 * i + 1]) == 0);
        int s, r;
        if (is64) {
            const long long* p = (const long long*)ei;
            s = (int)p[e];
            r = (int)p[NE + e];
        } else {
            s = ei[e];
            r = ei[NE + e];
        }
        s = min(max(s, 0), NN - 1);
        r = min(max(r, 0), NN - 1);
        g_send[e] = s;
        g_recv[e] = r;
        g_ord[e] = atomicAdd(&g_cnt[r], 1);
    } else {
        // W2/W3 -> fp16 mma B-fragments (K=64, N=64 each)
        int rel = blockIdx.x - CONV_BLKS;      // 0..7
        int which = rel >> 2;                  // 0 -> W2, 1 -> W3
        int idx = (rel & 3) * 256 + t;         // 0..1023
        const float* W = which ? W3 : W2;
        uint2* dst = which ? g_W3f : g_W2f;
        int lane = idx & 31;
        int ksnt = idx >> 5;
        int ks = ksnt >> 3, nt = ksnt & 7;
        int n  = nt * 8 + (lane >> 2);
        int k0 = ks * 16 + (lane & 3) * 2;
        float v00 = __ldg(&W[(size_t)k0 * 64 + n]);
        float v01 = __ldg(&W[(size_t)(k0 + 1) * 64 + n]);
        float v08 = __ldg(&W[(size_t)(k0 + 8) * 64 + n]);
        float v09 = __ldg(&W[(size_t)(k0 + 9) * 64 + n]);
        dst[idx] = make_uint2(pack_h2(v00, v01), pack_h2(v08, v09));
    }
}

// ---------------- scan (exclusive prefix over g_cnt; re-zeroes g_cnt) --------
__global__ void k_scan() {
    __shared__ int s[1024];
    const int t = threadIdx.x;
    const int CK = 25;
    const int base = t * CK;
    int loc[CK];
    int sum = 0;
#pragma unroll
    for (int i = 0; i < CK; i++) {
        int idx = base + i;
        int c = (idx < NN) ? g_cnt[idx] : 0;
        if (idx < NN) g_cnt[idx] = 0;
        loc[i] = sum;
        sum += c;
    }
    s[t] = sum;
    __syncthreads();
    for (int d = 1; d < 1024; d <<= 1) {
        int v = (t >= d) ? s[t - d] : 0;
        __syncthreads();
        s[t] += v;
        __syncthreads();
    }
    int pre = (t == 0) ? 0 : s[t - 1];
#pragma unroll
    for (int i = 0; i < CK; i++) {
        int idx = base + i;
        if (idx < NN) g_off[idx] = pre + loc[i];
    }
    if (t == 1023) g_off[NN] = s[1023];
}

// ---------------- scatter edge_attrs into rank order -------------------------
__global__ void k_scatter(const float* __restrict__ ea) {
    int e = blockIdx.x * 256 + threadIdx.x;
    if (e >= NE) return;
    int rk = g_off[g_recv[e]] + g_ord[e];
    const float4* src = (const float4*)&ea[(size_t)e * 16];
    float4* dst = (float4*)&g_sh[(size_t)rk * 16];
#pragma unroll
    for (int j = 0; j < 4; j++) dst[j] = src[j];
}

// ---------------- k_pre: r123 (HMMA L2/L3) + h GEMM + W4/Wout frag prep ------
static constexpr int R123N_BLKS = (NE + 127) / 128;  // 3907
static constexpr int HN_BLKS    = (NN + 15) / 16;    // 1563
static constexpr int BF_BLKS    = 32;                // 8192 W4 frags / 256 thr
static constexpr int OF_BLKS    = 64;                // 16384 Wout frags / 256 thr

// shared layout for the r123 variant (38.9 KB total)
static constexpr int P_A   = 0;        // 16384 B: 128 rows x 64 halves, SW128
static constexpr int P_B2  = 16384;    // 8192 B
static constexpr int P_B3  = 24576;    // 8192 B
static constexpr int P_EF  = 32768;    // 4096 B: 128 x 8 fp32
static constexpr int P_W1  = 36864;    // 2048 B: 8 x 64 fp32
static constexpr int P_SM  = 38912;

__global__ void __launch_bounds__(256) k_pre(
    const float* __restrict__ ef, const float* __restrict__ W1,
    const float* __restrict__ nf, const float* __restrict__ Wup,
    const float* __restrict__ W4, const float* __restrict__ Wout) {
    __shared__ __align__(16) unsigned char sm[P_SM];
    const int t = threadIdx.x;

    if (blockIdx.x < R123N_BLKS) {
        // ================= radial MLP: L1 fp32, L2/L3 HMMA fp16 ==============
        float* efs = (float*)(sm + P_EF);
        float* W1s = (float*)(sm + P_W1);
        uint2* B2  = (uint2*)(sm + P_B2);
        uint2* B3  = (uint2*)(sm + P_B3);
        const int e0 = blockIdx.x * 128;

        for (int i = t; i < 1024; i += 256) {
            int e = e0 + (i >> 3);
            efs[i] = (e < NE) ? ef[(size_t)e * 8 + (i & 7)] : 0.0f;
        }
        W1s[t] = __ldg(&W1[t]);
        W1s[t + 256] = __ldg(&W1[t + 256]);
        {
            const uint4* s2 = (const uint4*)g_W2f;
            const uint4* s3 = (const uint4*)g_W3f;
            uint4* d2 = (uint4*)B2;
            uint4* d3 = (uint4*)B3;
            for (int i = t; i < 512; i += 256) { d2[i] = s2[i]; d3[i] = s3[i]; }
        }
        __syncthreads();

        // ---- layer 1 (K=8, fp32) -> A tile fp16 SW128 ----
        {
            const int r  = t >> 1;
            const int c0 = (t & 1) * 32;
            float a[8];
#pragma unroll
            for (int k = 0; k < 8; k++) a[k] = efs[r * 8 + k];
#pragma unroll
            for (int j = 0; j < 32; j += 2) {
                float v0 = 0.f, v1 = 0.f;
#pragma unroll
                for (int k = 0; k < 8; k++) {
                    v0 += a[k] * W1s[k * 64 + c0 + j];
                    v1 += a[k] * W1s[k * 64 + c0 + j + 1];
                }
                unsigned off = SWZ128((unsigned)(r * 128 + (c0 + j) * 2));
                *(unsigned*)(sm + P_A + off) = pack_h2(silu(v0), silu(v1));
            }
        }
        __syncthreads();

        const int lane = t & 31, wid = t >> 5;
        const int mrow0 = wid * 16;
        const int arow = mrow0 + (lane & 15);
        const int acol = (lane >> 4) << 3;
        const unsigned abyte = (unsigned)(arow * 128 + acol * 2);
        const unsigned sbase = smem_u32(sm);
        const int r    = lane >> 2;
        const int row0 = mrow0 + r, row1 = row0 + 8;
        const int cp   = (lane & 3) << 1;

        // ---- layer 2 (HMMA) ----
        float acc[8][4];
#pragma unroll
        for (int i = 0; i < 8; i++)
#pragma unroll
            for (int j = 0; j < 4; j++) acc[i][j] = 0.0f;
#pragma unroll
        for (int ks = 0; ks < 4; ks++) {
            unsigned off = SWZ128(abyte + ks * 32);
            unsigned a0[4];
            ldmatrix_x4(a0, sbase + P_A + off);
#pragma unroll
            for (int nt = 0; nt < 8; nt++) {
                uint2 b = B2[(ks * 8 + nt) * 32 + lane];
                mma_f16(acc[nt], a0, b.x, b.y);
            }
        }
        __syncthreads();   // all ldmatrix reads done before overwrite
#pragma unroll
        for (int nt = 0; nt < 8; nt++) {
            int col = nt * 8 + cp;
            *(unsigned*)(sm + P_A + SWZ128((unsigned)(row0 * 128 + col * 2))) =
                pack_h2(silu(acc[nt][0]), silu(acc[nt][1]));
            *(unsigned*)(sm + P_A + SWZ128((unsigned)(row1 * 128 + col * 2))) =
                pack_h2(silu(acc[nt][2]), silu(acc[nt][3]));
        }
        __syncthreads();

        // ---- layer 3 (HMMA) ----
#pragma unroll
        for (int i = 0; i < 8; i++)
#pragma unroll
            for (int j = 0; j < 4; j++) acc[i][j] = 0.0f;
#pragma unroll
        for (int ks = 0; ks < 4; ks++) {
            unsigned off = SWZ128(abyte + ks * 32);
            unsigned a0[4];
            ldmatrix_x4(a0, sbase + P_A + off);
#pragma unroll
            for (int nt = 0; nt < 8; nt++) {
                uint2 b = B3[(ks * 8 + nt) * 32 + lane];
                mma_f16(acc[nt], a0, b.x, b.y);
            }
        }
        __syncthreads();
        // write silu(acc) LINEAR for coalesced store
#pragma unroll
        for (int nt = 0; nt < 8; nt++) {
            int col = nt * 8 + cp;
            *(unsigned*)(sm + P_A + (unsigned)(row0 * 128 + col * 2)) =
                pack_h2(silu(acc[nt][0]), silu(acc[nt][1]));
            *(unsigned*)(sm + P_A + (unsigned)(row1 * 128 + col * 2)) =
                pack_h2(silu(acc[nt][2]), silu(acc[nt][3]));
        }
        __syncthreads();
        for (int i = t; i < 1024; i += 256) {
            int rr = i >> 3;
            int e = e0 + rr;
            if (e < NE)
                *(uint4*)&g_x3f[(size_t)e * 64 + (i & 7) * 8] = ((uint4*)(sm + P_A))[i];
        }
    } else if (blockIdx.x < R123N_BLKS + HN_BLKS) {
        // ================= h = node_feats @ W_up (fp16 out) ==================
        float* fs = (float*)sm;   // 16 x 128 fp32 = 8 KB
        const int n0 = (blockIdx.x - R123N_BLKS) * 16;
        for (int i = t; i < 2048; i += 256) {
            int n = n0 + (i >> 7);
            fs[i] = (n < NN) ? nf[(size_t)n * CH + (i & 127)] : 0.0f;
        }
        __syncthreads();
        const int col = t & 127;
        const int g   = t >> 7;   // node group 0/1 -> 8 nodes each
        float acc[8];
#pragma unroll
        for (int i = 0; i < 8; i++) acc[i] = 0.0f;
        for (int k = 0; k < CH; k++) {
            float wv = __ldg(&Wup[k * CH + col]);
#pragma unroll
            for (int i = 0; i < 8; i++) acc[i] += fs[(g * 8 + i) * CH + k] * wv;
        }
#pragma unroll
        for (int i = 0; i < 8; i++) {
            int n = n0 + g * 8 + i;
            if (n < NN) g_hh[(size_t)n * CH + col] = __float2half_rn(acc[i]);
        }
    } else if (blockIdx.x < R123N_BLKS + HN_BLKS + BF_BLKS) {
        // ================= W4 -> fp16 mma B-fragments ========================
        int idx = (blockIdx.x - R123N_BLKS - HN_BLKS) * 256 + t;
        if (idx < 8192) {
            int chunk = idx >> 10;
            int w     = idx & 1023;
            int ksnt  = w >> 5;
            int lane  = w & 31;
            int ks = ksnt >> 3, nt = ksnt & 7;
            int n  = chunk * 64 + nt * 8 + (lane >> 2);
            int k0 = ks * 16 + (lane & 3) * 2;
            float v00 = __ldg(&W4[(size_t)k0 * 512 + n]);
            float v01 = __ldg(&W4[(size_t)(k0 + 1) * 512 + n]);
            float v08 = __ldg(&W4[(size_t)(k0 + 8) * 512 + n]);
            float v09 = __ldg(&W4[(size_t)(k0 + 9) * 512 + n]);
            g_Bf[idx] = make_uint2(pack_h2(v00, v01), pack_h2(v08, v09));
        }
    } else {
        // ================= Wout -> fp16 mma B-fragments ======================
        int idx = (blockIdx.x - R123N_BLKS - HN_BLKS - BF_BLKS) * 256 + t;
        if (idx < 16384) {
            int path = idx >> 12;
            int w    = idx & 4095;
            int ks   = w >> 9;
            int rest = w & 511;
            int ntg  = rest >> 5;
            int lane = rest & 31;
            int d  = ntg * 8 + (lane >> 2);
            int k0 = ks * 16 + (lane & 3) * 2;
            const float* Wl = Wout + path * CH * CH;
            float v00 = __ldg(&Wl[(size_t)k0 * 128 + d]);
            float v01 = __ldg(&Wl[(size_t)(k0 + 1) * 128 + d]);
            float v08 = __ldg(&Wl[(size_t)(k0 + 8) * 128 + d]);
            float v09 = __ldg(&Wl[(size_t)(k0 + 9) * 128 + d]);
            g_Of[idx] = make_uint2(pack_h2(v00, v01), pack_h2(v08, v09));
        }
    }
}

// ---------------- layer 4: HMMA fp16 GEMM, chunk-merged (unchanged R13) ------
static constexpr int R4_OFF_A0  = 0;
static constexpr int R4_OFF_B   = 16384;
static constexpr int R4_OFF_STG = 24576;
static constexpr int R4_STG_U   = 36;
static constexpr int R4_OFF_SS  = 43008;
static constexpr int R4_OFF_RS  = 43520;
static constexpr int R4_SMEM    = 44032;

__global__ void __launch_bounds__(256, 4) k_r4() {
    extern __shared__ __align__(16) unsigned char smem[];
    uint2*    Bs    = (uint2*)(smem + R4_OFF_B);
    unsigned* stage = (unsigned*)(smem + R4_OFF_STG);
    int*      ssm   = (int*)(smem + R4_OFF_SS);
    int*      rsm   = (int*)(smem + R4_OFF_RS);
    const int t  = threadIdx.x;
    const int e0 = blockIdx.x * 128;

    for (int i = t; i < 1024; i += 256) {
        int r = i >> 3;
        int c = i & 7;
        int e = e0 + r;
        uint4 v = make_uint4(0u, 0u, 0u, 0u);
        if (e < NE) v = *(const uint4*)&g_x3f[(size_t)e * 64 + c * 8];
        unsigned off = SWZ128((unsigned)(r * 128 + c * 16));
        *(uint4*)(smem + R4_OFF_A0 + off) = v;
    }
    if (t < 128) {
        int e = e0 + t;
        ssm[t] = (e < NE) ? g_send[e] : 0;
        rsm[t] = (e < NE) ? (g_off[g_recv[e]] + g_ord[e]) : 0;
    }

    const int lane = t & 31, wid = t >> 5;
    const int mrow0 = wid * 16;
    const int arow = mrow0 + (lane & 15);
    const int acol = (lane >> 4) << 3;
    const unsigned abyte = (unsigned)(arow * 128 + acol * 2);
    const unsigned sbase = smem_u32(smem);
    const int r    = lane >> 2;
    const int row0 = mrow0 + r, row1 = row0 + 8;
    const int cp   = (lane & 3) << 1;

#pragma unroll 1
    for (int chunk = 0; chunk < 8; chunk++) {
        {
            const uint4* src = (const uint4*)(g_Bf + chunk * 1024);
            uint4* dst = (uint4*)Bs;
            for (int i = t; i < 512; i += 256) dst[i] = src[i];
        }
        __syncthreads();

        float acc[8][4];
#pragma unroll
        for (int i = 0; i < 8; i++)
#pragma unroll
            for (int j = 0; j < 4; j++) acc[i][j] = 0.0f;

#pragma unroll
        for (int ks = 0; ks < 4; ks++) {
            unsigned off = SWZ128(abyte + ks * 32);
            unsigned a0[4];
            ldmatrix_x4(a0, sbase + R4_OFF_A0 + off);
#pragma unroll
            for (int nt = 0; nt < 8; nt++) {
                uint2 b = Bs[(ks * 8 + nt) * 32 + lane];
                mma_f16(acc[nt], a0, b.x, b.y);
            }
        }

        const int s0 = ssm[row0], s1 = ssm[row1];
        const int hb = (chunk & 1) * 64 + cp;
#pragma unroll
        for (int nt = 0; nt < 8; nt++) {
            int colu = nt * 4 + (lane & 3);
            float2 f0 = __half22float2(
                __ldg((const __half2*)&g_hh[(size_t)s0 * CH + hb + nt * 8]));
            float2 f1 = __half22float2(
                __ldg((const __half2*)&g_hh[(size_t)s1 * CH + hb + nt * 8]));
            stage[row0 * R4_STG_U + colu] = pack_h2(acc[nt][0] * f0.x, acc[nt][1] * f0.y);
            stage[row1 * R4_STG_U + colu] = pack_h2(acc[nt][2] * f1.x, acc[nt][3] * f1.y);
        }
        __syncthreads();

#pragma unroll
        for (int it = 0; it < 4; it++) {
            int idx = it * 256 + t;
            int row = idx >> 3;
            int q   = idx & 7;
            if (e0 + row < NE) {
                uint4 v = *(uint4*)&stage[row * R4_STG_U + q * 4];
                *(uint4*)&g_wh[(size_t)rsm[row] * 512 + chunk * 64 + q * 8] = v;
            }
        }
    }
}

// ---------------- segmented aggregation: streaming fp16 reads, fp16 write ----
__global__ void k_agg() {
    const int n = blockIdx.x;
    const int c = threadIdx.x;
    float acc[16];
#pragma unroll
    for (int m = 0; m < 16; m++) acc[m] = 0.0f;
    const int lo = g_off[n], hi = g_off[n + 1];

    int i = lo;
    for (; i + 2 <= hi; i += 2) {
        const __half* wa = g_wh + (size_t)i * 512;
        const __half* wb = wa + 512;
        float a0 = __half2float(wa[c]),       a1 = __half2float(wa[128 + c]);
        float a2 = __half2float(wa[256 + c]), a3 = __half2float(wa[384 + c]);
        float b0 = __half2float(wb[c]),       b1 = __half2float(wb[128 + c]);
        float b2 = __half2float(wb[256 + c]), b3 = __half2float(wb[384 + c]);
        const float* sa = g_sh + (size_t)i * 16;
        const float* sb = sa + 16;
        acc[0] += __ldg(&sa[0]) * a0 + __ldg(&sb[0]) * b0;
#pragma unroll
        for (int m = 1; m < 4; m++) acc[m] += __ldg(&sa[m]) * a1 + __ldg(&sb[m]) * b1;
#pragma unroll
        for (int m = 4; m < 9; m++) acc[m] += __ldg(&sa[m]) * a2 + __ldg(&sb[m]) * b2;
#pragma unroll
        for (int m = 9; m < 16; m++) acc[m] += __ldg(&sa[m]) * a3 + __ldg(&sb[m]) * b3;
    }
    if (i < hi) {
        const __half* wa = g_wh + (size_t)i * 512;
        float a0 = __half2float(wa[c]),       a1 = __half2float(wa[128 + c]);
        float a2 = __half2float(wa[256 + c]), a3 = __half2float(wa[384 + c]);
        const float* sa = g_sh + (size_t)i * 16;
        acc[0] += __ldg(&sa[0]) * a0;
#pragma unroll
        for (int m = 1; m < 4; m++) acc[m] += __ldg(&sa[m]) * a1;
#pragma unroll
        for (int m = 4; m < 9; m++) acc[m] += __ldg(&sa[m]) * a2;
#pragma unroll
        for (int m = 9; m < 16; m++) acc[m] += __ldg(&sa[m]) * a3;
    }
    const float inv = 0.05f;
#pragma unroll
    for (int m = 0; m < 16; m++)
        g_aggh[(size_t)n * 2048 + m * 128 + c] = __float2half_rn(acc[m] * inv);
}

// ---------------- out transform: HMMA fp16 (single launch, range dispatch) ---
template <int ML, int NB, int OFFM, int COLOFF, int PATH>
__device__ __forceinline__ void out_body(int blk, unsigned char* osm,
                                         float* __restrict__ out) {
    constexpr int NR = ML * NB;  // <= 64
    const int t  = threadIdx.x;
    const int n0 = blk * NB;

    for (int g = t; g < 1024; g += 256) {
        int r  = g >> 4;
        int c8 = g & 15;
        uint4 v = make_uint4(0u, 0u, 0u, 0u);
        if (r < NR) {
            int n = n0 + r / ML;
            if (n < NN)
                v = *(const uint4*)&g_aggh[(size_t)n * 2048 +
                                           (OFFM + r % ML) * 128 + c8 * 8];
        }
        unsigned off = SWZ128((unsigned)((r * 2 + (c8 >> 3)) * 128 + (c8 & 7) * 16));
        *(uint4*)(osm + off) = v;
    }
    __syncthreads();

    const int lane = t & 31, wid = t >> 5;
    const int rt = wid & 3, ch = wid >> 2;
    const int lr = rt * 16 + (lane & 15);
    const unsigned sbase = smem_u32(osm);

    float acc[8][4];
#pragma unroll
    for (int i = 0; i < 8; i++)
#pragma unroll
        for (int j = 0; j < 4; j++) acc[i][j] = 0.0f;

#pragma unroll
    for (int ks = 0; ks < 8; ks++) {
        unsigned abyte = (unsigned)((lr * 2 + (ks >= 4 ? 1 : 0)) * 128 +
                                    (ks & 3) * 32 + ((lane >> 4) << 4));
        unsigned a[4];
        ldmatrix_x4(a, sbase + SWZ128(abyte));
#pragma unroll
        for (int nt = 0; nt < 8; nt++) {
            uint2 b = __ldg(&g_Of[(((PATH * 8 + ks) * 16 + ch * 8 + nt) * 32) + lane]);
            mma_f16(acc[nt], a, b.x, b.y);
        }
    }
    __syncthreads();

    float* As = (float*)osm;
    const int r0 = rt * 16 + (lane >> 2), r1 = r0 + 8;
    const int cp = (lane & 3) << 1;
#pragma unroll
    for (int nt = 0; nt < 8; nt++) {
        int col = ch * 64 + nt * 8 + cp;
        As[r0 * 129 + col]     = acc[nt][0];
        As[r0 * 129 + col + 1] = acc[nt][1];
        As[r1 * 129 + col]     = acc[nt][2];
        As[r1 * 129 + col + 1] = acc[nt][3];
    }
    __syncthreads();

    for (int idx = t; idx < NB * ML * 128; idx += 256) {
        int n_l = idx / (ML * 128);
        int rem = idx - n_l * (ML * 128);
        int d = rem / ML;
        int m = rem - d * ML;
        int n = n0 + n_l;
        if (n < NN)
            out[(size_t)n * OUTW + COLOFF + rem] = As[(n_l * ML + m) * 129 + d];
    }
}

static constexpr int OUT_B0 = (NN + 63) / 64;
static constexpr int OUT_B1 = (NN + 20) / 21;
static constexpr int OUT_B2 = (NN + 11) / 12;
static constexpr int OUT_B3 = (NN + 8) / 9;
static constexpr int OUT_BLKS = OUT_B0 + OUT_B1 + OUT_B2 + OUT_B3;

__global__ void __launch_bounds__(256, 4) k_out_all(float* __restrict__ out) {
    __shared__ __align__(16) unsigned char osm[64 * 129 * 4];
    int b = blockIdx.x;
    if (b < OUT_B0) {
        out_body<1, 64, 0, 0, 0>(b, osm, out);
    } else if (b < OUT_B0 + OUT_B1) {
        out_body<3, 21, 1, 128, 1>(b - OUT_B0, osm, out);
    } else if (b < OUT_B0 + OUT_B1 + OUT_B2) {
        out_body<5, 12, 4, 512, 2>(b - OUT_B0 - OUT_B1, osm, out);
    } else {
        out_body<7, 9, 9, 1152, 3>(b - OUT_B0 - OUT_B1 - OUT_B2, osm, out);
    }
}

// ---------------- one-body term ----------------------------------------------
__global__ void k_ob(const float* __restrict__ pf, const float* __restrict__ nf,
                     const float* __restrict__ lc, const float* __restrict__ Wp,
                     const float* __restrict__ Wn, const float* __restrict__ Wc,
                     float* __restrict__ out) {
    __shared__ float pfs[16 * 16];
    __shared__ float nfs[16 * 128];
    __shared__ float lcs[16];
    const int t  = threadIdx.x;
    const int n0 = blockIdx.x * 16;
    for (int i = t; i < 16 * 16; i += 128) {
        int n = n0 + i / 16;
        pfs[i] = (n < NN) ? pf[(size_t)n * 16 + (i & 15)] * 0.1f : 0.0f;
    }
    for (int i = t; i < 16 * 128; i += 128) {
        int n = n0 + i / 128;
        nfs[i] = (n < NN) ? nf[(size_t)n * 128 + (i & 127)] : 0.0f;
    }
    if (t < 16) {
        int n = n0 + t;
        lcs[t] = (n < NN) ? lc[n] : 0.0f;
    }
    __syncthreads();
    float acc[16];
    float wc = __ldg(&Wc[t]);
#pragma unroll
    for (int i = 0; i < 16; i++) acc[i] = lcs[i] * wc;
    for (int k = 0; k < 16; k++) {
        float wv = __ldg(&Wp[k * 128 + t]);
#pragma unroll
        for (int i = 0; i < 16; i++) acc[i] += pfs[i * 16 + k] * wv;
    }
    for (int k = 0; k < 128; k++) {
        float wv = __ldg(&Wn[k * 128 + t]);
#pragma unroll
        for (int i = 0; i < 16; i++) acc[i] += nfs[i * 128 + k] * wv;
    }
#pragma unroll
    for (int i = 0; i < 16; i++) {
        int n = n0 + i;
        if (n < NN) out[(size_t)n * OUTW + t] += acc[i];
    }
}

// ---------------- launch -----------------------------------------------------
extern "C" void kernel_launch(void* const* d_in, const int* in_sizes, int n_in,
                              void* d_out, int out_size) {
    const float* node_feats = (const float*)d_in[1];
    const float* edge_attrs = (const float*)d_in[2];
    const float* edge_feats = (const float*)d_in[3];
    const int*   edge_index = (const int*)d_in[4];
    const float* potential  = (const float*)d_in[5];
    const float* charges    = (const float*)d_in[6];
    const float* W_up = (const float*)d_in[7];
    const float* W1   = (const float*)d_in[8];
    const float* W2   = (const float*)d_in[9];
    const float* W3   = (const float*)d_in[10];
    const float* W4   = (const float*)d_in[11];
    const float* Wout = (const float*)d_in[12];
    const float* Wp   = (const float*)d_in[13];
    const float* Wn   = (const float*)d_in[14];
    const float* Wc   = (const float*)d_in[15];
    float*       out  = (float*)d_out;

    cudaFuncSetAttribute(k_r4, cudaFuncAttributeMaxDynamicSharedMemorySize, R4_SMEM);

    k_convert<<<CONV_BLKS + 8, 256>>>(edge_index, W2, W3);             // 0
    k_scan<<<1, 1024>>>();                                             // 1
    k_scatter<<<(NE + 255) / 256, 256>>>(edge_attrs);                  // 2
    k_pre<<<R123N_BLKS + HN_BLKS + BF_BLKS + OF_BLKS, 256>>>(          // 3 <- profiled
        edge_feats, W1, node_feats, W_up, W4, Wout);
    k_r4<<<(NE + 127) / 128, 256, R4_SMEM>>>();                        // 4
    k_agg<<<NN, 128>>>();                                              // 5
    k_out_all<<<OUT_BLKS, 256>>>(out);                                 // 6
    k_ob<<<(NN + 15) / 16, 128>>>(potential, node_feats, charges,      // 7
                                  Wp, Wn, Wc, out);
}

// round 15
// speedup vs baseline: 1.3978x; 1.1514x over previous
#include <cuda_runtime.h>
#include <cuda_fp16.h>

static constexpr int NN   = 25000;
static constexpr int NE   = 500000;
static constexpr int CH   = 128;
static constexpr int OUTW = 2048;

// ---------------- scratch (static device globals; no allocation allowed) ----
__device__ __half g_hh[NN * CH];                  // 6.4 MB (h, fp16)
__device__ __half g_x3f[(size_t)NE * 64];         // 64 MB  (x3, fp16)
__device__ __half g_wh[(size_t)NE * 512];         // 512 MB (rank-ordered rows, fp16)
__device__ uint2  g_Bf[8192];                     // W4 fp16 mma B-fragments (64 KB)
__device__ uint2  g_Of[16384];                    // Wout fp16 mma B-fragments (128 KB)
__device__ uint2  g_W2f[1024];                    // W2 fp16 mma B-fragments (8 KB)
__device__ uint2  g_W3f[1024];                    // W3 fp16 mma B-fragments (8 KB)
__device__ int    g_cnt[NN];                      // zero-init; scan re-zeroes
__device__ int    g_off[NN + 1];
__device__ int    g_ord[NE];                      // per-receiver ordinal
__device__ int    g_sorted[NE];                   // rank -> edge id
__device__ int    g_send[NE];
__device__ int    g_recv[NE];

__device__ __forceinline__ float silu(float x) {
    return __fdividef(x, 1.0f + __expf(-x));
}

// ---------------- mma helpers (legacy HMMA path, sm_80+; works on sm_100) ----
#define SWZ128(off) ((off) ^ (((off) >> 3) & 0x70))

__device__ __forceinline__ unsigned smem_u32(const void* p) {
    unsigned a;
    asm("{ .reg .u64 t; cvta.to.shared.u64 t, %1; cvt.u32.u64 %0, t; }"
        : "=r"(a) : "l"(p));
    return a;
}
__device__ __forceinline__ void ldmatrix_x4(unsigned* r, unsigned addr) {
    asm volatile("ldmatrix.sync.aligned.m8n8.x4.shared.b16 {%0,%1,%2,%3}, [%4];"
                 : "=r"(r[0]), "=r"(r[1]), "=r"(r[2]), "=r"(r[3]) : "r"(addr));
}
__device__ __forceinline__ void mma_f16(float* d, const unsigned* a,
                                        unsigned b0, unsigned b1) {
    asm volatile(
        "mma.sync.aligned.m16n8k16.row.col.f32.f16.f16.f32 "
        "{%0,%1,%2,%3}, {%4,%5,%6,%7}, {%8,%9}, {%0,%1,%2,%3};"
        : "+f"(d[0]), "+f"(d[1]), "+f"(d[2]), "+f"(d[3])
        : "r"(a[0]), "r"(a[1]), "r"(a[2]), "r"(a[3]), "r"(b0), "r"(b1));
}
__device__ __forceinline__ unsigned pack_h2(float x, float y) {
    __half2 q = __floats2half2_rn(x, y);
    return *(unsigned*)&q;
}

// ---------------- convert: dtype detect + hist/ordinal + W2/W3 frag prep -----
static constexpr int CONV_BLKS = (NE + 255) / 256;  // 1954

__global__ void __launch_bounds__(256) k_convert(const int* __restrict__ ei,
                                                 const float* __restrict__ W2,
                                                 const float* __restrict__ W3) {
    const int t = threadIdx.x;
    if (blockIdx.x < CONV_BLKS) {
        int e = blockIdx.x * 256 + t;
        if (e >= NE) return;
        bool is64 = true;
#pragma unroll
        for (int i = 0; i < 8; i++) is64 &= (__ldg(&ei[2 * i + 1]) == 0);
        int s, r;
        if (is64) {
            const long long* p = (const long long*)ei;
            s = (int)p[e];
            r = (int)p[NE + e];
        } else {
            s = ei[e];
            r = ei[NE + e];
        }
        s = min(max(s, 0), NN - 1);
        r = min(max(r, 0), NN - 1);
        g_send[e] = s;
        g_recv[e] = r;
        g_ord[e] = atomicAdd(&g_cnt[r], 1);
    } else {
        int rel = blockIdx.x - CONV_BLKS;
        int which = rel >> 2;
        int idx = (rel & 3) * 256 + t;
        const float* W = which ? W3 : W2;
        uint2* dst = which ? g_W3f : g_W2f;
        int lane = idx & 31;
        int ksnt = idx >> 5;
        int ks = ksnt >> 3, nt = ksnt & 7;
        int n  = nt * 8 + (lane >> 2);
        int k0 = ks * 16 + (lane & 3) * 2;
        float v00 = __ldg(&W[(size_t)k0 * 64 + n]);
        float v01 = __ldg(&W[(size_t)(k0 + 1) * 64 + n]);
        float v08 = __ldg(&W[(size_t)(k0 + 8) * 64 + n]);
        float v09 = __ldg(&W[(size_t)(k0 + 9) * 64 + n]);
        dst[idx] = make_uint2(pack_h2(v00, v01), pack_h2(v08, v09));
    }
}

// ---------------- scan (exclusive prefix over g_cnt; re-zeroes g_cnt) --------
__global__ void k_scan() {
    __shared__ int s[1024];
    const int t = threadIdx.x;
    const int CK = 25;
    const int base = t * CK;
    int loc[CK];
    int sum = 0;
#pragma unroll
    for (int i = 0; i < CK; i++) {
        int idx = base + i;
        int c = (idx < NN) ? g_cnt[idx] : 0;
        if (idx < NN) g_cnt[idx] = 0;
        loc[i] = sum;
        sum += c;
    }
    s[t] = sum;
    __syncthreads();
    for (int d = 1; d < 1024; d <<= 1) {
        int v = (t >= d) ? s[t - d] : 0;
        __syncthreads();
        s[t] += v;
        __syncthreads();
    }
    int pre = (t == 0) ? 0 : s[t - 1];
#pragma unroll
    for (int i = 0; i < CK; i++) {
        int idx = base + i;
        if (idx < NN) g_off[idx] = pre + loc[i];
    }
    if (t == 1023) g_off[NN] = s[1023];
}

// ---------------- sort index: rank -> edge id ---------------------------------
__global__ void k_sortidx() {
    int e = blockIdx.x * 256 + threadIdx.x;
    if (e < NE) g_sorted[g_off[g_recv[e]] + g_ord[e]] = e;
}

// ---------------- k_pre: r123 (HMMA L2/L3) + h GEMM + W4/Wout frag prep ------
static constexpr int R123N_BLKS = (NE + 127) / 128;  // 3907
static constexpr int HN_BLKS    = (NN + 15) / 16;    // 1563
static constexpr int BF_BLKS    = 32;
static constexpr int OF_BLKS    = 64;

static constexpr int P_A   = 0;
static constexpr int P_B2  = 16384;
static constexpr int P_B3  = 24576;
static constexpr int P_EF  = 32768;
static constexpr int P_W1  = 36864;
static constexpr int P_SM  = 38912;

__global__ void __launch_bounds__(256) k_pre(
    const float* __restrict__ ef, const float* __restrict__ W1,
    const float* __restrict__ nf, const float* __restrict__ Wup,
    const float* __restrict__ W4, const float* __restrict__ Wout) {
    __shared__ __align__(16) unsigned char sm[P_SM];
    const int t = threadIdx.x;

    if (blockIdx.x < R123N_BLKS) {
        float* efs = (float*)(sm + P_EF);
        float* W1s = (float*)(sm + P_W1);
        uint2* B2  = (uint2*)(sm + P_B2);
        uint2* B3  = (uint2*)(sm + P_B3);
        const int e0 = blockIdx.x * 128;

        for (int i = t; i < 1024; i += 256) {
            int e = e0 + (i >> 3);
            efs[i] = (e < NE) ? ef[(size_t)e * 8 + (i & 7)] : 0.0f;
        }
        W1s[t] = __ldg(&W1[t]);
        W1s[t + 256] = __ldg(&W1[t + 256]);
        {
            const uint4* s2 = (const uint4*)g_W2f;
            const uint4* s3 = (const uint4*)g_W3f;
            uint4* d2 = (uint4*)B2;
            uint4* d3 = (uint4*)B3;
            for (int i = t; i < 512; i += 256) { d2[i] = s2[i]; d3[i] = s3[i]; }
        }
        __syncthreads();

        {
            const int r  = t >> 1;
            const int c0 = (t & 1) * 32;
            float a[8];
#pragma unroll
            for (int k = 0; k < 8; k++) a[k] = efs[r * 8 + k];
#pragma unroll
            for (int j = 0; j < 32; j += 2) {
                float v0 = 0.f, v1 = 0.f;
#pragma unroll
                for (int k = 0; k < 8; k++) {
                    v0 += a[k] * W1s[k * 64 + c0 + j];
                    v1 += a[k] * W1s[k * 64 + c0 + j + 1];
                }
                unsigned off = SWZ128((unsigned)(r * 128 + (c0 + j) * 2));
                *(unsigned*)(sm + P_A + off) = pack_h2(silu(v0), silu(v1));
            }
        }
        __syncthreads();

        const int lane = t & 31, wid = t >> 5;
        const int mrow0 = wid * 16;
        const int arow = mrow0 + (lane & 15);
        const int acol = (lane >> 4) << 3;
        const unsigned abyte = (unsigned)(arow * 128 + acol * 2);
        const unsigned sbase = smem_u32(sm);
        const int r    = lane >> 2;
        const int row0 = mrow0 + r, row1 = row0 + 8;
        const int cp   = (lane & 3) << 1;

        float acc[8][4];
#pragma unroll
        for (int i = 0; i < 8; i++)
#pragma unroll
            for (int j = 0; j < 4; j++) acc[i][j] = 0.0f;
#pragma unroll
        for (int ks = 0; ks < 4; ks++) {
            unsigned off = SWZ128(abyte + ks * 32);
            unsigned a0[4];
            ldmatrix_x4(a0, sbase + P_A + off);
#pragma unroll
            for (int nt = 0; nt < 8; nt++) {
                uint2 b = B2[(ks * 8 + nt) * 32 + lane];
                mma_f16(acc[nt], a0, b.x, b.y);
            }
        }
        __syncthreads();
#pragma unroll
        for (int nt = 0; nt < 8; nt++) {
            int col = nt * 8 + cp;
            *(unsigned*)(sm + P_A + SWZ128((unsigned)(row0 * 128 + col * 2))) =
                pack_h2(silu(acc[nt][0]), silu(acc[nt][1]));
            *(unsigned*)(sm + P_A + SWZ128((unsigned)(row1 * 128 + col * 2))) =
                pack_h2(silu(acc[nt][2]), silu(acc[nt][3]));
        }
        __syncthreads();

#pragma unroll
        for (int i = 0; i < 8; i++)
#pragma unroll
            for (int j = 0; j < 4; j++) acc[i][j] = 0.0f;
#pragma unroll
        for (int ks = 0; ks < 4; ks++) {
            unsigned off = SWZ128(abyte + ks * 32);
            unsigned a0[4];
            ldmatrix_x4(a0, sbase + P_A + off);
#pragma unroll
            for (int nt = 0; nt < 8; nt++) {
                uint2 b = B3[(ks * 8 + nt) * 32 + lane];
                mma_f16(acc[nt], a0, b.x, b.y);
            }
        }
        __syncthreads();
#pragma unroll
        for (int nt = 0; nt < 8; nt++) {
            int col = nt * 8 + cp;
            *(unsigned*)(sm + P_A + (unsigned)(row0 * 128 + col * 2)) =
                pack_h2(silu(acc[nt][0]), silu(acc[nt][1]));
            *(unsigned*)(sm + P_A + (unsigned)(row1 * 128 + col * 2)) =
                pack_h2(silu(acc[nt][2]), silu(acc[nt][3]));
        }
        __syncthreads();
        for (int i = t; i < 1024; i += 256) {
            int rr = i >> 3;
            int e = e0 + rr;
            if (e < NE)
                *(uint4*)&g_x3f[(size_t)e * 64 + (i & 7) * 8] = ((uint4*)(sm + P_A))[i];
        }
    } else if (blockIdx.x < R123N_BLKS + HN_BLKS) {
        float* fs = (float*)sm;
        const int n0 = (blockIdx.x - R123N_BLKS) * 16;
        for (int i = t; i < 2048; i += 256) {
            int n = n0 + (i >> 7);
            fs[i] = (n < NN) ? nf[(size_t)n * CH + (i & 127)] : 0.0f;
        }
        __syncthreads();
        const int col = t & 127;
        const int g   = t >> 7;
        float acc[8];
#pragma unroll
        for (int i = 0; i < 8; i++) acc[i] = 0.0f;
        for (int k = 0; k < CH; k++) {
            float wv = __ldg(&Wup[k * CH + col]);
#pragma unroll
            for (int i = 0; i < 8; i++) acc[i] += fs[(g * 8 + i) * CH + k] * wv;
        }
#pragma unroll
        for (int i = 0; i < 8; i++) {
            int n = n0 + g * 8 + i;
            if (n < NN) g_hh[(size_t)n * CH + col] = __float2half_rn(acc[i]);
        }
    } else if (blockIdx.x < R123N_BLKS + HN_BLKS + BF_BLKS) {
        int idx = (blockIdx.x - R123N_BLKS - HN_BLKS) * 256 + t;
        if (idx < 8192) {
            int chunk = idx >> 10;
            int w     = idx & 1023;
            int ksnt  = w >> 5;
            int lane  = w & 31;
            int ks = ksnt >> 3, nt = ksnt & 7;
            int n  = chunk * 64 + nt * 8 + (lane >> 2);
            int k0 = ks * 16 + (lane & 3) * 2;
            float v00 = __ldg(&W4[(size_t)k0 * 512 + n]);
            float v01 = __ldg(&W4[(size_t)(k0 + 1) * 512 + n]);
            float v08 = __ldg(&W4[(size_t)(k0 + 8) * 512 + n]);
            float v09 = __ldg(&W4[(size_t)(k0 + 9) * 512 + n]);
            g_Bf[idx] = make_uint2(pack_h2(v00, v01), pack_h2(v08, v09));
        }
    } else {
        int idx = (blockIdx.x - R123N_BLKS - HN_BLKS - BF_BLKS) * 256 + t;
        if (idx < 16384) {
            int path = idx >> 12;
            int w    = idx & 4095;
            int ks   = w >> 9;
            int rest = w & 511;
            int ntg  = rest >> 5;
            int lane = rest & 31;
            int d  = ntg * 8 + (lane >> 2);
            int k0 = ks * 16 + (lane & 3) * 2;
            const float* Wl = Wout + path * CH * CH;
            float v00 = __ldg(&Wl[(size_t)k0 * 128 + d]);
            float v01 = __ldg(&Wl[(size_t)(k0 + 1) * 128 + d]);
            float v08 = __ldg(&Wl[(size_t)(k0 + 8) * 128 + d]);
            float v09 = __ldg(&Wl[(size_t)(k0 + 9) * 128 + d]);
            g_Of[idx] = make_uint2(pack_h2(v00, v01), pack_h2(v08, v09));
        }
    }
}

// ---------------- layer 4: HMMA fp16 GEMM, chunk-merged (unchanged R13) ------
static constexpr int R4_OFF_A0  = 0;
static constexpr int R4_OFF_B   = 16384;
static constexpr int R4_OFF_STG = 24576;
static constexpr int R4_STG_U   = 36;
static constexpr int R4_OFF_SS  = 43008;
static constexpr int R4_OFF_RS  = 43520;
static constexpr int R4_SMEM    = 44032;

__global__ void __launch_bounds__(256, 4) k_r4() {
    extern __shared__ __align__(16) unsigned char smem[];
    uint2*    Bs    = (uint2*)(smem + R4_OFF_B);
    unsigned* stage = (unsigned*)(smem + R4_OFF_STG);
    int*      ssm   = (int*)(smem + R4_OFF_SS);
    int*      rsm   = (int*)(smem + R4_OFF_RS);
    const int t  = threadIdx.x;
    const int e0 = blockIdx.x * 128;

    for (int i = t; i < 1024; i += 256) {
        int r = i >> 3;
        int c = i & 7;
        int e = e0 + r;
        uint4 v = make_uint4(0u, 0u, 0u, 0u);
        if (e < NE) v = *(const uint4*)&g_x3f[(size_t)e * 64 + c * 8];
        unsigned off = SWZ128((unsigned)(r * 128 + c * 16));
        *(uint4*)(smem + R4_OFF_A0 + off) = v;
    }
    if (t < 128) {
        int e = e0 + t;
        ssm[t] = (e < NE) ? g_send[e] : 0;
        rsm[t] = (e < NE) ? (g_off[g_recv[e]] + g_ord[e]) : 0;
    }

    const int lane = t & 31, wid = t >> 5;
    const int mrow0 = wid * 16;
    const int arow = mrow0 + (lane & 15);
    const int acol = (lane >> 4) << 3;
    const unsigned abyte = (unsigned)(arow * 128 + acol * 2);
    const unsigned sbase = smem_u32(smem);
    const int r    = lane >> 2;
    const int row0 = mrow0 + r, row1 = row0 + 8;
    const int cp   = (lane & 3) << 1;

#pragma unroll 1
    for (int chunk = 0; chunk < 8; chunk++) {
        {
            const uint4* src = (const uint4*)(g_Bf + chunk * 1024);
            uint4* dst = (uint4*)Bs;
            for (int i = t; i < 512; i += 256) dst[i] = src[i];
        }
        __syncthreads();

        float acc[8][4];
#pragma unroll
        for (int i = 0; i < 8; i++)
#pragma unroll
            for (int j = 0; j < 4; j++) acc[i][j] = 0.0f;

#pragma unroll
        for (int ks = 0; ks < 4; ks++) {
            unsigned off = SWZ128(abyte + ks * 32);
            unsigned a0[4];
            ldmatrix_x4(a0, sbase + R4_OFF_A0 + off);
#pragma unroll
            for (int nt = 0; nt < 8; nt++) {
                uint2 b = Bs[(ks * 8 + nt) * 32 + lane];
                mma_f16(acc[nt], a0, b.x, b.y);
            }
        }

        const int s0 = ssm[row0], s1 = ssm[row1];
        const int hb = (chunk & 1) * 64 + cp;
#pragma unroll
        for (int nt = 0; nt < 8; nt++) {
            int colu = nt * 4 + (lane & 3);
            float2 f0 = __half22float2(
                __ldg((const __half2*)&g_hh[(size_t)s0 * CH + hb + nt * 8]));
            float2 f1 = __half22float2(
                __ldg((const __half2*)&g_hh[(size_t)s1 * CH + hb + nt * 8]));
            stage[row0 * R4_STG_U + colu] = pack_h2(acc[nt][0] * f0.x, acc[nt][1] * f0.y);
            stage[row1 * R4_STG_U + colu] = pack_h2(acc[nt][2] * f1.x, acc[nt][3] * f1.y);
        }
        __syncthreads();

#pragma unroll
        for (int it = 0; it < 4; it++) {
            int idx = it * 256 + t;
            int row = idx >> 3;
            int q   = idx & 7;
            if (e0 + row < NE) {
                uint4 v = *(uint4*)&stage[row * R4_STG_U + q * 4];
                *(uint4*)&g_wh[(size_t)rsm[row] * 512 + chunk * 64 + q * 8] = v;
            }
        }
    }
}

// ---------------- out transform: fused segment-agg + HMMA fp16 ---------------
// Per block: NB nodes (64 rows of agg slice). Phase 1: warp-per-node agg from
// rank-contiguous g_wh + edge_attrs (fp32 regs) -> fp16 A-tile (SW128).
// Phase 2: HMMA vs Wout fragments; coalesced fp32 store.
template <int ML, int NB, int OFFM, int COLOFF, int PATH>
__device__ __forceinline__ void out_body(int blk, unsigned char* osm,
                                         const float* __restrict__ ea,
                                         float* __restrict__ out) {
    constexpr int NR = ML * NB;  // <= 64
    const int t  = threadIdx.x;
    const int n0 = blk * NB;
    const int lane = t & 31, wid = t >> 5;

    // ---- phase 1: aggregation into A tile ----
    for (int nl = wid; nl < NB; nl += 8) {
        int n = n0 + nl;
        float acc[ML][4];
#pragma unroll
        for (int m = 0; m < ML; m++)
#pragma unroll
            for (int j = 0; j < 4; j++) acc[m][j] = 0.0f;
        if (n < NN) {
            const int lo = g_off[n], hi = g_off[n + 1];
            for (int i = lo; i < hi; i++) {
                int e = g_sorted[i];
                uint2 wv = __ldg((const uint2*)&g_wh[(size_t)i * 512 +
                                                     PATH * 128 + lane * 4]);
                float2 w0 = __half22float2(*(__half2*)&wv.x);
                float2 w1 = __half22float2(*(__half2*)&wv.y);
#pragma unroll
                for (int m = 0; m < ML; m++) {
                    float sh = __ldg(&ea[(size_t)e * 16 + OFFM + m]);
                    acc[m][0] += sh * w0.x;
                    acc[m][1] += sh * w0.y;
                    acc[m][2] += sh * w1.x;
                    acc[m][3] += sh * w1.y;
                }
            }
        }
        const int c0 = lane * 4;
#pragma unroll
        for (int m = 0; m < ML; m++) {
            int rr = nl * ML + m;
            unsigned byteoff = (unsigned)((rr * 2 + (c0 >> 6)) * 128 + (c0 & 63) * 2);
            *(uint2*)(osm + SWZ128(byteoff)) =
                make_uint2(pack_h2(acc[m][0] * 0.05f, acc[m][1] * 0.05f),
                           pack_h2(acc[m][2] * 0.05f, acc[m][3] * 0.05f));
        }
    }
    __syncthreads();

    // ---- phase 2: HMMA ----
    const int rt = wid & 3, ch = wid >> 2;
    const int lr = rt * 16 + (lane & 15);
    const unsigned sbase = smem_u32(osm);

    float acc[8][4];
#pragma unroll
    for (int i = 0; i < 8; i++)
#pragma unroll
        for (int j = 0; j < 4; j++) acc[i][j] = 0.0f;

#pragma unroll
    for (int ks = 0; ks < 8; ks++) {
        unsigned abyte = (unsigned)((lr * 2 + (ks >= 4 ? 1 : 0)) * 128 +
                                    (ks & 3) * 32 + ((lane >> 4) << 4));
        unsigned a[4];
        ldmatrix_x4(a, sbase + SWZ128(abyte));
#pragma unroll
        for (int nt = 0; nt < 8; nt++) {
            uint2 b = __ldg(&g_Of[(((PATH * 8 + ks) * 16 + ch * 8 + nt) * 32) + lane]);
            mma_f16(acc[nt], a, b.x, b.y);
        }
    }
    __syncthreads();

    float* As = (float*)osm;
    const int r0 = rt * 16 + (lane >> 2), r1 = r0 + 8;
    const int cp = (lane & 3) << 1;
#pragma unroll
    for (int nt = 0; nt < 8; nt++) {
        int col = ch * 64 + nt * 8 + cp;
        As[r0 * 129 + col]     = acc[nt][0];
        As[r0 * 129 + col + 1] = acc[nt][1];
        As[r1 * 129 + col]     = acc[nt][2];
        As[r1 * 129 + col + 1] = acc[nt][3];
    }
    __syncthreads();

    for (int idx = t; idx < NB * ML * 128; idx += 256) {
        int n_l = idx / (ML * 128);
        int rem = idx - n_l * (ML * 128);
        int d = rem / ML;
        int m = rem - d * ML;
        int n = n0 + n_l;
        if (n < NN)
            out[(size_t)n * OUTW + COLOFF + rem] = As[(n_l * ML + m) * 129 + d];
    }
}

static constexpr int OUT_B0 = (NN + 63) / 64;
static constexpr int OUT_B1 = (NN + 20) / 21;
static constexpr int OUT_B2 = (NN + 11) / 12;
static constexpr int OUT_B3 = (NN + 8) / 9;
static constexpr int OUT_BLKS = OUT_B0 + OUT_B1 + OUT_B2 + OUT_B3;

__global__ void __launch_bounds__(256, 4) k_out_all(const float* __restrict__ ea,
                                                    float* __restrict__ out) {
    __shared__ __align__(16) unsigned char osm[64 * 129 * 4];
    int b = blockIdx.x;
    if (b < OUT_B0) {
        out_body<1, 64, 0, 0, 0>(b, osm, ea, out);
    } else if (b < OUT_B0 + OUT_B1) {
        out_body<3, 21, 1, 128, 1>(b - OUT_B0, osm, ea, out);
    } else if (b < OUT_B0 + OUT_B1 + OUT_B2) {
        out_body<5, 12, 4, 512, 2>(b - OUT_B0 - OUT_B1, osm, ea, out);
    } else {
        out_body<7, 9, 9, 1152, 3>(b - OUT_B0 - OUT_B1 - OUT_B2, osm, ea, out);
    }
}

// ---------------- one-body term ----------------------------------------------
__global__ void k_ob(const float* __restrict__ pf, const float* __restrict__ nf,
                     const float* __restrict__ lc, const float* __restrict__ Wp,
                     const float* __restrict__ Wn, const float* __restrict__ Wc,
                     float* __restrict__ out) {
    __shared__ float pfs[16 * 16];
    __shared__ float nfs[16 * 128];
    __shared__ float lcs[16];
    const int t  = threadIdx.x;
    const int n0 = blockIdx.x * 16;
    for (int i = t; i < 16 * 16; i += 128) {
        int n = n0 + i / 16;
        pfs[i] = (n < NN) ? pf[(size_t)n * 16 + (i & 15)] * 0.1f : 0.0f;
    }
    for (int i = t; i < 16 * 128; i += 128) {
        int n = n0 + i / 128;
        nfs[i] = (n < NN) ? nf[(size_t)n * 128 + (i & 127)] : 0.0f;
    }
    if (t < 16) {
        int n = n0 + t;
        lcs[t] = (n < NN) ? lc[n] : 0.0f;
    }
    __syncthreads();
    float acc[16];
    float wc = __ldg(&Wc[t]);
#pragma unroll
    for (int i = 0; i < 16; i++) acc[i] = lcs[i] * wc;
    for (int k = 0; k < 16; k++) {
        float wv = __ldg(&Wp[k * 128 + t]);
#pragma unroll
        for (int i = 0; i < 16; i++) acc[i] += pfs[i * 16 + k] * wv;
    }
    for (int k = 0; k < 128; k++) {
        float wv = __ldg(&Wn[k * 128 + t]);
#pragma unroll
        for (int i = 0; i < 16; i++) acc[i] += nfs[i * 128 + k] * wv;
    }
#pragma unroll
    for (int i = 0; i < 16; i++) {
        int n = n0 + i;
        if (n < NN) out[(size_t)n * OUTW + t] += acc[i];
    }
}

// ---------------- launch -----------------------------------------------------
extern "C" void kernel_launch(void* const* d_in, const int* in_sizes, int n_in,
                              void* d_out, int out_size) {
    const float* node_feats = (const float*)d_in[1];
    const float* edge_attrs = (const float*)d_in[2];
    const float* edge_feats = (const float*)d_in[3];
    const int*   edge_index = (const int*)d_in[4];
    const float* potential  = (const float*)d_in[5];
    const float* charges    = (const float*)d_in[6];
    const float* W_up = (const float*)d_in[7];
    const float* W1   = (const float*)d_in[8];
    const float* W2   = (const float*)d_in[9];
    const float* W3   = (const float*)d_in[10];
    const float* W4   = (const float*)d_in[11];
    const float* Wout = (const float*)d_in[12];
    const float* Wp   = (const float*)d_in[13];
    const float* Wn   = (const float*)d_in[14];
    const float* Wc   = (const float*)d_in[15];
    float*       out  = (float*)d_out;

    cudaFuncSetAttribute(k_r4, cudaFuncAttributeMaxDynamicSharedMemorySize, R4_SMEM);

    k_convert<<<CONV_BLKS + 8, 256>>>(edge_index, W2, W3);             // 0
    k_scan<<<1, 1024>>>();                                             // 1
    k_pre<<<R123N_BLKS + HN_BLKS + BF_BLKS + OF_BLKS, 256>>>(          // 2
        edge_feats, W1, node_feats, W_up, W4, Wout);
    k_r4<<<(NE + 127) / 128, 256, R4_SMEM>>>();                        // 3 <- profiled
    k_sortidx<<<(NE + 255) / 256, 256>>>();                            // 4
    k_out_all<<<OUT_BLKS, 256>>>(edge_attrs, out);                     // 5
    k_ob<<<(NN + 15) / 16, 128>>>(potential, node_feats, charges,      // 6
                                  Wp, Wn, Wc, out);
}